// round 1
// baseline (speedup 1.0000x reference)
#include <cuda_runtime.h>
#include <cstdint>

#define FULLMASK 0xffffffffu

// Scratch (device globals: allocation-free rule).
// Layout [B*H, N, hd] for Q/K/V; [B, N, C] for attention output X.
static __device__ float g_Q[2 * 16 * 2048 * 64];
static __device__ float g_K[2 * 16 * 2048 * 64];
static __device__ float g_V[2 * 16 * 2048 * 64];
static __device__ float g_X[2 * 2048 * 1024];

__device__ __forceinline__ uint32_t f2tf32(float f) {
    uint32_t u;
    asm("cvt.rna.tf32.f32 %0, %1;" : "=r"(u) : "f"(f));
    return u;
}

__device__ __forceinline__ void mma8(float c[4], const uint32_t a[4], const uint32_t b[2]) {
    asm volatile(
        "mma.sync.aligned.m16n8k8.row.col.f32.tf32.tf32.f32 "
        "{%0,%1,%2,%3}, {%4,%5,%6,%7}, {%8,%9}, {%0,%1,%2,%3};"
        : "+f"(c[0]), "+f"(c[1]), "+f"(c[2]), "+f"(c[3])
        : "r"(a[0]), "r"(a[1]), "r"(a[2]), "r"(a[3]),
          "r"(b[0]), "r"(b[1]));
}

// ---------------------------------------------------------------------------
// NT GEMM: C[m, j] = sum_k A[m,k] * W[j,k]
// MODE 0: QKV projection. A is the virtual concat [q|k|v] (M=4096, K=3072),
//         output scattered into g_Q/g_K/g_V as [B*H, N, hd].
// MODE 1: output projection. A = g_X (M=4096, K=1024), out = C + bias.
// Tiles: BM=BN=64, BK=16; 128 threads (4 warps, 2x2), warp tile 32x32.
// ---------------------------------------------------------------------------
template <int MODE>
__global__ void __launch_bounds__(128) gemm_tf32_nt(
    const float* __restrict__ Aq, const float* __restrict__ Ak,
    const float* __restrict__ Av, const float* __restrict__ W,
    const float* __restrict__ bias, float* __restrict__ out,
    int K, int Nc)
{
    // stride 20 => conflict-free fragment loads (20*g + t distinct mod 32)
    // and 80B rows (16B-aligned) for uint4 stores.
    __shared__ __align__(16) uint32_t As[64][20];
    __shared__ __align__(16) uint32_t Bs[64][20];

    const int tid  = threadIdx.x;
    const int lane = tid & 31;
    const int w    = tid >> 5;
    const int gid  = lane >> 2;
    const int tig  = lane & 3;
    const int warp_m = (w >> 1) * 32;
    const int warp_n = (w & 1) * 32;
    const int mBase  = blockIdx.y * 64;
    const int nBase  = blockIdx.x * 64;

    const int m_l = tid >> 2;          // rows 0..31 (second load handles +32)
    const int k_l = (tid & 3) * 4;     // 0,4,8,12

    float acc[2][4][4];
#pragma unroll
    for (int i = 0; i < 2; i++)
#pragma unroll
        for (int j = 0; j < 4; j++)
#pragma unroll
            for (int e = 0; e < 4; e++) acc[i][j][e] = 0.f;

    auto loadA = [&](int kt, int mrow) -> float4 {
        const int gm = mBase + mrow;
        const int gk = kt * 16 + k_l;
        if (MODE == 0) {
            const int which = gk >> 10;  // 0=q, 1=k, 2=v (1024-col slabs)
            const float* p = (which == 0) ? Aq : ((which == 1) ? Ak : Av);
            return *(const float4*)(p + (size_t)gm * 1024 + (gk & 1023));
        } else {
            return *(const float4*)((const float*)g_X + (size_t)gm * K + gk);
        }
    };
    auto loadB = [&](int kt, int nrow) -> float4 {
        return *(const float4*)(W + (size_t)(nBase + nrow) * K + kt * 16 + k_l);
    };

    const int NK = K / 16;
    float4 ra0 = loadA(0, m_l), ra1 = loadA(0, m_l + 32);
    float4 rb0 = loadB(0, m_l), rb1 = loadB(0, m_l + 32);

    for (int kt = 0; kt < NK; kt++) {
        // store current tile (rounded to tf32)
        *(uint4*)&As[m_l][k_l]      = make_uint4(f2tf32(ra0.x), f2tf32(ra0.y), f2tf32(ra0.z), f2tf32(ra0.w));
        *(uint4*)&As[m_l + 32][k_l] = make_uint4(f2tf32(ra1.x), f2tf32(ra1.y), f2tf32(ra1.z), f2tf32(ra1.w));
        *(uint4*)&Bs[m_l][k_l]      = make_uint4(f2tf32(rb0.x), f2tf32(rb0.y), f2tf32(rb0.z), f2tf32(rb0.w));
        *(uint4*)&Bs[m_l + 32][k_l] = make_uint4(f2tf32(rb1.x), f2tf32(rb1.y), f2tf32(rb1.z), f2tf32(rb1.w));
        __syncthreads();

        if (kt + 1 < NK) {  // prefetch next tile into registers
            ra0 = loadA(kt + 1, m_l);
            ra1 = loadA(kt + 1, m_l + 32);
            rb0 = loadB(kt + 1, m_l);
            rb1 = loadB(kt + 1, m_l + 32);
        }

#pragma unroll
        for (int kk8 = 0; kk8 < 16; kk8 += 8) {
            uint32_t a[2][4];
#pragma unroll
            for (int mt = 0; mt < 2; mt++) {
                const int r = warp_m + mt * 16 + gid;
                a[mt][0] = As[r][kk8 + tig];
                a[mt][1] = As[r + 8][kk8 + tig];
                a[mt][2] = As[r][kk8 + tig + 4];
                a[mt][3] = As[r + 8][kk8 + tig + 4];
            }
#pragma unroll
            for (int nt = 0; nt < 4; nt++) {
                uint32_t b[2];
                const int cn = warp_n + nt * 8 + gid;
                b[0] = Bs[cn][kk8 + tig];
                b[1] = Bs[cn][kk8 + tig + 4];
                mma8(acc[0][nt], a[0], b);
                mma8(acc[1][nt], a[1], b);
            }
        }
        __syncthreads();
    }

    // Epilogue. C fragment layout: c0(row g, col 2t), c1(row g, col 2t+1),
    // c2(row g+8, col 2t), c3(row g+8, col 2t+1).
#pragma unroll
    for (int mt = 0; mt < 2; mt++) {
        const int row0 = mBase + warp_m + mt * 16 + gid;
#pragma unroll
        for (int nt = 0; nt < 4; nt++) {
            const int col = nBase + warp_n + nt * 8 + tig * 2;
            if (MODE == 0) {
                // col j -> (t, h, d); row m -> (b, n). Scatter into [B*H, N, hd].
                const int t = col >> 10, h = (col >> 6) & 15, d = col & 63;
                float* dst = (t == 0) ? g_Q : ((t == 1) ? g_K : g_V);
                const size_t base0 =
                    ((size_t)((row0 >> 11) * 16 + h) * 2048 + (row0 & 2047)) * 64 + d;
                *(float2*)(dst + base0)          = make_float2(acc[mt][nt][0], acc[mt][nt][1]);
                *(float2*)(dst + base0 + 8 * 64) = make_float2(acc[mt][nt][2], acc[mt][nt][3]);
            } else {
                const float b0 = bias[col], b1 = bias[col + 1];
                *(float2*)(out + (size_t)row0 * Nc + col) =
                    make_float2(acc[mt][nt][0] + b0, acc[mt][nt][1] + b1);
                *(float2*)(out + (size_t)(row0 + 8) * Nc + col) =
                    make_float2(acc[mt][nt][2] + b0, acc[mt][nt][3] + b1);
            }
        }
    }
}

// ---------------------------------------------------------------------------
// Flash attention: grid (qtile=16, bh=32), 256 threads (8 warps).
// Each warp owns 16 Q rows (Q fragments pinned in registers, pre-scaled).
// K/V 64-row tiles staged in smem as tf32; online softmax; P is re-fragmented
// from mma-C layout to mma-A layout with intra-quad shuffles.
// ---------------------------------------------------------------------------
__global__ void __launch_bounds__(256) attn_flash()
{
    // Ks stride 68: S-mma B-frag access (4*gid + tig) conflict-free.
    // Vs stride 72: PV-mma B-frag access (8*tig + gid) conflict-free.
    __shared__ __align__(16) uint32_t Ks[64][68];
    __shared__ __align__(16) uint32_t Vs[64][72];

    const int bh    = blockIdx.y;
    const int qbase = blockIdx.x * 128;
    const int tid   = threadIdx.x;
    const int lane  = tid & 31;
    const int w     = tid >> 5;
    const int gid   = lane >> 2;
    const int tig   = lane & 3;

    const float* Qp = g_Q + (size_t)bh * (2048 * 64);
    const float* Kp = g_K + (size_t)bh * (2048 * 64);
    const float* Vp = g_V + (size_t)bh * (2048 * 64);

    // Q fragments for this warp's 16 rows (scale folded in here).
    uint32_t qa[8][4];
    {
        const float* q0 = Qp + (size_t)(qbase + w * 16 + gid) * 64;
        const float* q8 = q0 + 8 * 64;
#pragma unroll
        for (int kk = 0; kk < 8; kk++) {
            qa[kk][0] = f2tf32(q0[kk * 8 + tig] * 0.125f);
            qa[kk][1] = f2tf32(q8[kk * 8 + tig] * 0.125f);
            qa[kk][2] = f2tf32(q0[kk * 8 + tig + 4] * 0.125f);
            qa[kk][3] = f2tf32(q8[kk * 8 + tig + 4] * 0.125f);
        }
    }

    float o[8][4];
#pragma unroll
    for (int i = 0; i < 8; i++)
#pragma unroll
        for (int j = 0; j < 4; j++) o[i][j] = 0.f;
    float m0 = -1e30f, m1 = -1e30f, l0 = 0.f, l1 = 0.f;

    for (int kv = 0; kv < 2048; kv += 64) {
        __syncthreads();  // protect previous iteration's smem reads
#pragma unroll
        for (int i = 0; i < 4; i++) {
            const int vv = tid + 256 * i;
            const int r  = vv >> 4;
            const int c  = (vv & 15) * 4;
            const float4 kf = *(const float4*)(Kp + (size_t)(kv + r) * 64 + c);
            const float4 vf = *(const float4*)(Vp + (size_t)(kv + r) * 64 + c);
            *(uint4*)&Ks[r][c] = make_uint4(f2tf32(kf.x), f2tf32(kf.y), f2tf32(kf.z), f2tf32(kf.w));
            *(uint4*)&Vs[r][c] = make_uint4(f2tf32(vf.x), f2tf32(vf.y), f2tf32(vf.z), f2tf32(vf.w));
        }
        __syncthreads();

        // S = (Q*scale) K^T : 16 x 64 per warp
        float s[8][4];
#pragma unroll
        for (int i = 0; i < 8; i++)
#pragma unroll
            for (int j = 0; j < 4; j++) s[i][j] = 0.f;
#pragma unroll
        for (int kk = 0; kk < 8; kk++) {
#pragma unroll
            for (int nt = 0; nt < 8; nt++) {
                uint32_t b[2];
                b[0] = Ks[nt * 8 + gid][kk * 8 + tig];
                b[1] = Ks[nt * 8 + gid][kk * 8 + tig + 4];
                mma8(s[nt], qa[kk], b);
            }
        }

        // Online softmax. Rows gid (c0,c1) / gid+8 (c2,c3); row stats shared
        // across the 4-lane quad -> butterfly shuffles xor 1, xor 2.
        float mt0 = -1e30f, mt1 = -1e30f;
#pragma unroll
        for (int nt = 0; nt < 8; nt++) {
            mt0 = fmaxf(mt0, fmaxf(s[nt][0], s[nt][1]));
            mt1 = fmaxf(mt1, fmaxf(s[nt][2], s[nt][3]));
        }
        mt0 = fmaxf(mt0, __shfl_xor_sync(FULLMASK, mt0, 1));
        mt0 = fmaxf(mt0, __shfl_xor_sync(FULLMASK, mt0, 2));
        mt1 = fmaxf(mt1, __shfl_xor_sync(FULLMASK, mt1, 1));
        mt1 = fmaxf(mt1, __shfl_xor_sync(FULLMASK, mt1, 2));

        const float mn0 = fmaxf(m0, mt0), mn1 = fmaxf(m1, mt1);
        const float f0 = __expf(m0 - mn0), f1 = __expf(m1 - mn1);

        float rs0 = 0.f, rs1 = 0.f;
#pragma unroll
        for (int nt = 0; nt < 8; nt++) {
            s[nt][0] = __expf(s[nt][0] - mn0);
            s[nt][1] = __expf(s[nt][1] - mn0);
            s[nt][2] = __expf(s[nt][2] - mn1);
            s[nt][3] = __expf(s[nt][3] - mn1);
            rs0 += s[nt][0] + s[nt][1];
            rs1 += s[nt][2] + s[nt][3];
        }
        rs0 += __shfl_xor_sync(FULLMASK, rs0, 1);
        rs0 += __shfl_xor_sync(FULLMASK, rs0, 2);
        rs1 += __shfl_xor_sync(FULLMASK, rs1, 1);
        rs1 += __shfl_xor_sync(FULLMASK, rs1, 2);

        l0 = l0 * f0 + rs0;
        l1 = l1 * f1 + rs1;
        m0 = mn0;
        m1 = mn1;
#pragma unroll
        for (int nt = 0; nt < 8; nt++) {
            o[nt][0] *= f0; o[nt][1] *= f0;
            o[nt][2] *= f1; o[nt][3] *= f1;
        }

        // O += P V. Re-fragment P (C layout -> A layout) via quad shuffles.
        const int src0 = (lane & ~3) | (tig >> 1);
        const int src1 = src0 + 2;
        const bool odd = tig & 1;
#pragma unroll
        for (int kt = 0; kt < 8; kt++) {
            const float v00 = __shfl_sync(FULLMASK, s[kt][0], src0);
            const float v01 = __shfl_sync(FULLMASK, s[kt][1], src0);
            const float v10 = __shfl_sync(FULLMASK, s[kt][2], src0);
            const float v11 = __shfl_sync(FULLMASK, s[kt][3], src0);
            const float u00 = __shfl_sync(FULLMASK, s[kt][0], src1);
            const float u01 = __shfl_sync(FULLMASK, s[kt][1], src1);
            const float u10 = __shfl_sync(FULLMASK, s[kt][2], src1);
            const float u11 = __shfl_sync(FULLMASK, s[kt][3], src1);
            uint32_t pa[4];
            pa[0] = f2tf32(odd ? v01 : v00);  // P[gid   ][8kt+tig]
            pa[1] = f2tf32(odd ? v11 : v10);  // P[gid+8 ][8kt+tig]
            pa[2] = f2tf32(odd ? u01 : u00);  // P[gid   ][8kt+tig+4]
            pa[3] = f2tf32(odd ? u11 : u10);  // P[gid+8 ][8kt+tig+4]
#pragma unroll
            for (int nt = 0; nt < 8; nt++) {
                uint32_t b[2];
                b[0] = Vs[kt * 8 + tig][nt * 8 + gid];
                b[1] = Vs[kt * 8 + tig + 4][nt * 8 + gid];
                mma8(o[nt], pa, b);
            }
        }
    }

    // Normalize and write to g_X[b, n, h*64 + d].
    const float inv0 = 1.f / l0, inv1 = 1.f / l1;
    const int b = bh >> 4, h = bh & 15;
    const int n0 = qbase + w * 16 + gid;
    float* x0 = g_X + ((size_t)b * 2048 + n0) * 1024 + h * 64;
    float* x8 = x0 + 8 * 1024;
#pragma unroll
    for (int nt = 0; nt < 8; nt++) {
        const int d = nt * 8 + tig * 2;
        *(float2*)(x0 + d) = make_float2(o[nt][0] * inv0, o[nt][1] * inv0);
        *(float2*)(x8 + d) = make_float2(o[nt][2] * inv1, o[nt][3] * inv1);
    }
}

// ---------------------------------------------------------------------------
extern "C" void kernel_launch(void* const* d_in, const int* in_sizes, int n_in,
                              void* d_out, int out_size)
{
    const float* q     = (const float*)d_in[0];
    const float* k     = (const float*)d_in[1];
    const float* v     = (const float*)d_in[2];
    const float* Wqkv  = (const float*)d_in[3];
    const float* Wproj = (const float*)d_in[4];
    const float* bproj = (const float*)d_in[5];
    float* out = (float*)d_out;

    // 1) fused QKV projection -> g_Q/g_K/g_V  (M=4096, N=3072, K=3072)
    gemm_tf32_nt<0><<<dim3(48, 64), 128>>>(q, k, v, Wqkv, nullptr, nullptr, 3072, 3072);
    // 2) flash attention -> g_X
    attn_flash<<<dim3(16, 32), 256>>>();
    // 3) output projection + bias -> d_out  (M=4096, N=1024, K=1024)
    gemm_tf32_nt<1><<<dim3(16, 64), 128>>>(nullptr, nullptr, nullptr, Wproj, bproj, out, 1024, 1024);
}

// round 2
// speedup vs baseline: 1.2337x; 1.2337x over previous
#include <cuda_runtime.h>
#include <cstdint>

#define FULLMASK 0xffffffffu

// Scratch (device globals: allocation-free rule).
static __device__ float g_Q[2 * 16 * 2048 * 64];
static __device__ float g_K[2 * 16 * 2048 * 64];
static __device__ float g_V[2 * 16 * 2048 * 64];
static __device__ float g_X[2 * 2048 * 1024];

__device__ __forceinline__ uint32_t f2tf32(float f) {
    uint32_t u;
    asm("cvt.rna.tf32.f32 %0, %1;" : "=r"(u) : "f"(f));
    return u;
}

__device__ __forceinline__ void mma8(float c[4], const uint32_t a[4], const uint32_t b[2]) {
    asm volatile(
        "mma.sync.aligned.m16n8k8.row.col.f32.tf32.tf32.f32 "
        "{%0,%1,%2,%3}, {%4,%5,%6,%7}, {%8,%9}, {%0,%1,%2,%3};"
        : "+f"(c[0]), "+f"(c[1]), "+f"(c[2]), "+f"(c[3])
        : "r"(a[0]), "r"(a[1]), "r"(a[2]), "r"(a[3]),
          "r"(b[0]), "r"(b[1]));
}

// ---------------------------------------------------------------------------
// NT GEMM: C[m, j] = sum_k A[m,k] * W[j,k]
// Block 128x128xBK16, 128 threads (4 warps, 2x2), warp tile 64x64.
// Double-buffered XOR-swizzled smem (no padding): word = r*16 + ((g^( (r>>1)&3 ))<<2) + (c&3).
// MODE 0: QKV projection (A = virtual [q|k|v], scatter out to g_Q/g_K/g_V).
// MODE 1: output projection (A = g_X, out = C + bias).
// ---------------------------------------------------------------------------
template <int MODE>
__global__ void __launch_bounds__(128) gemm_tf32_nt(
    const float* __restrict__ Aq, const float* __restrict__ Ak,
    const float* __restrict__ Av, const float* __restrict__ W,
    const float* __restrict__ bias, float* __restrict__ out,
    int K, int Nc)
{
    __shared__ __align__(16) uint32_t As[2][128 * 16];
    __shared__ __align__(16) uint32_t Bs[2][128 * 16];

    const int tid  = threadIdx.x;
    const int lane = tid & 31;
    const int w    = tid >> 5;
    const int gid  = lane >> 2;
    const int tig  = lane & 3;
    const int warp_m = (w >> 1) * 64;
    const int warp_n = (w & 1) * 64;
    const int mBase  = blockIdx.y * 128;
    const int nBase  = blockIdx.x * 128;

    // staging thread mapping: 4 rows each for A and B
    const int row_l = tid >> 2;            // 0..31 (+32*i)
    const int g_l   = tid & 3;             // 16B granule within row
    const int k_l   = g_l * 4;
    const int gp    = g_l ^ ((row_l >> 1) & 3);  // swizzled granule (const: (row>>1)&3 invariant under +32)

    // fragment-read column offsets (swizzle term = gid>>1, constant per thread)
    const int s = gid >> 1;
    int co[4];
#pragma unroll
    for (int j = 0; j < 4; j++) co[j] = ((j ^ s) << 2) + tig;

    // fragment row bases
    int rA[4], rB[8];
#pragma unroll
    for (int mt = 0; mt < 4; mt++) rA[mt] = (warp_m + mt * 16 + gid) * 16;
#pragma unroll
    for (int nt = 0; nt < 8; nt++) rB[nt] = (warp_n + nt * 8 + gid) * 16;

    float acc[4][8][4];
#pragma unroll
    for (int i = 0; i < 4; i++)
#pragma unroll
        for (int j = 0; j < 8; j++)
#pragma unroll
            for (int e = 0; e < 4; e++) acc[i][j][e] = 0.f;

    auto loadA = [&](int kt, int mrow) -> float4 {
        const int gm = mBase + mrow;
        const int gk = kt * 16 + k_l;
        if (MODE == 0) {
            const int which = gk >> 10;  // 0=q, 1=k, 2=v
            const float* p = (which == 0) ? Aq : ((which == 1) ? Ak : Av);
            return *(const float4*)(p + (size_t)gm * 1024 + (gk & 1023));
        } else {
            return *(const float4*)((const float*)g_X + (size_t)gm * K + gk);
        }
    };
    auto loadB = [&](int kt, int nrow) -> float4 {
        return *(const float4*)(W + (size_t)(nBase + nrow) * K + kt * 16 + k_l);
    };

    const int NK = K / 16;
    float4 ra[4], rb[4];

#pragma unroll
    for (int i = 0; i < 4; i++) {
        ra[i] = loadA(0, row_l + 32 * i);
        rb[i] = loadB(0, row_l + 32 * i);
    }
#pragma unroll
    for (int i = 0; i < 4; i++) {
        const int r = row_l + 32 * i;
        *(uint4*)&As[0][r * 16 + gp * 4] =
            make_uint4(f2tf32(ra[i].x), f2tf32(ra[i].y), f2tf32(ra[i].z), f2tf32(ra[i].w));
        *(uint4*)&Bs[0][r * 16 + gp * 4] =
            make_uint4(f2tf32(rb[i].x), f2tf32(rb[i].y), f2tf32(rb[i].z), f2tf32(rb[i].w));
    }
    __syncthreads();

    for (int kt = 0; kt < NK; kt++) {
        const int cur = kt & 1;
        const bool more = (kt + 1 < NK);
        if (more) {
#pragma unroll
            for (int i = 0; i < 4; i++) {
                ra[i] = loadA(kt + 1, row_l + 32 * i);
                rb[i] = loadB(kt + 1, row_l + 32 * i);
            }
        }

#pragma unroll
        for (int h = 0; h < 2; h++) {     // kk8 = 8h ; col granules j0, j0+1
            const int j0 = 2 * h;
            uint32_t a[4][4], b[8][2];
#pragma unroll
            for (int mt = 0; mt < 4; mt++) {
                a[mt][0] = As[cur][rA[mt] + co[j0]];
                a[mt][1] = As[cur][rA[mt] + 128 + co[j0]];      // +8 rows = +128 words
                a[mt][2] = As[cur][rA[mt] + co[j0 + 1]];
                a[mt][3] = As[cur][rA[mt] + 128 + co[j0 + 1]];
            }
#pragma unroll
            for (int nt = 0; nt < 8; nt++) {
                b[nt][0] = Bs[cur][rB[nt] + co[j0]];
                b[nt][1] = Bs[cur][rB[nt] + co[j0 + 1]];
            }
#pragma unroll
            for (int mt = 0; mt < 4; mt++)
#pragma unroll
                for (int nt = 0; nt < 8; nt++)
                    mma8(acc[mt][nt], a[mt], b[nt]);
        }

        if (more) {
            const int nxt = 1 - cur;
#pragma unroll
            for (int i = 0; i < 4; i++) {
                const int r = row_l + 32 * i;
                *(uint4*)&As[nxt][r * 16 + gp * 4] =
                    make_uint4(f2tf32(ra[i].x), f2tf32(ra[i].y), f2tf32(ra[i].z), f2tf32(ra[i].w));
                *(uint4*)&Bs[nxt][r * 16 + gp * 4] =
                    make_uint4(f2tf32(rb[i].x), f2tf32(rb[i].y), f2tf32(rb[i].z), f2tf32(rb[i].w));
            }
        }
        __syncthreads();
    }

    // Epilogue. C frag: c0(row g, col 2t), c1(row g, col 2t+1), c2(+8, 2t), c3(+8, 2t+1).
#pragma unroll
    for (int mt = 0; mt < 4; mt++) {
        const int row0 = mBase + warp_m + mt * 16 + gid;
#pragma unroll
        for (int nt = 0; nt < 8; nt++) {
            const int col = nBase + warp_n + nt * 8 + tig * 2;
            if (MODE == 0) {
                const int t = col >> 10, hh = (col >> 6) & 15, d = col & 63;
                float* dst = (t == 0) ? g_Q : ((t == 1) ? g_K : g_V);
                const size_t base0 =
                    ((size_t)((row0 >> 11) * 16 + hh) * 2048 + (row0 & 2047)) * 64 + d;
                *(float2*)(dst + base0)          = make_float2(acc[mt][nt][0], acc[mt][nt][1]);
                *(float2*)(dst + base0 + 8 * 64) = make_float2(acc[mt][nt][2], acc[mt][nt][3]);
            } else {
                const float b0 = bias[col], b1 = bias[col + 1];
                *(float2*)(out + (size_t)row0 * Nc + col) =
                    make_float2(acc[mt][nt][0] + b0, acc[mt][nt][1] + b1);
                *(float2*)(out + (size_t)(row0 + 8) * Nc + col) =
                    make_float2(acc[mt][nt][2] + b0, acc[mt][nt][3] + b1);
            }
        }
    }
}

// ---------------------------------------------------------------------------
// Flash attention (unchanged from R1): grid (16, 32), 256 threads.
// ---------------------------------------------------------------------------
__global__ void __launch_bounds__(256) attn_flash()
{
    __shared__ __align__(16) uint32_t Ks[64][68];
    __shared__ __align__(16) uint32_t Vs[64][72];

    const int bh    = blockIdx.y;
    const int qbase = blockIdx.x * 128;
    const int tid   = threadIdx.x;
    const int lane  = tid & 31;
    const int w     = tid >> 5;
    const int gid   = lane >> 2;
    const int tig   = lane & 3;

    const float* Qp = g_Q + (size_t)bh * (2048 * 64);
    const float* Kp = g_K + (size_t)bh * (2048 * 64);
    const float* Vp = g_V + (size_t)bh * (2048 * 64);

    uint32_t qa[8][4];
    {
        const float* q0 = Qp + (size_t)(qbase + w * 16 + gid) * 64;
        const float* q8 = q0 + 8 * 64;
#pragma unroll
        for (int kk = 0; kk < 8; kk++) {
            qa[kk][0] = f2tf32(q0[kk * 8 + tig] * 0.125f);
            qa[kk][1] = f2tf32(q8[kk * 8 + tig] * 0.125f);
            qa[kk][2] = f2tf32(q0[kk * 8 + tig + 4] * 0.125f);
            qa[kk][3] = f2tf32(q8[kk * 8 + tig + 4] * 0.125f);
        }
    }

    float o[8][4];
#pragma unroll
    for (int i = 0; i < 8; i++)
#pragma unroll
        for (int j = 0; j < 4; j++) o[i][j] = 0.f;
    float m0 = -1e30f, m1 = -1e30f, l0 = 0.f, l1 = 0.f;

    for (int kv = 0; kv < 2048; kv += 64) {
        __syncthreads();
#pragma unroll
        for (int i = 0; i < 4; i++) {
            const int vv = tid + 256 * i;
            const int r  = vv >> 4;
            const int c  = (vv & 15) * 4;
            const float4 kf = *(const float4*)(Kp + (size_t)(kv + r) * 64 + c);
            const float4 vf = *(const float4*)(Vp + (size_t)(kv + r) * 64 + c);
            *(uint4*)&Ks[r][c] = make_uint4(f2tf32(kf.x), f2tf32(kf.y), f2tf32(kf.z), f2tf32(kf.w));
            *(uint4*)&Vs[r][c] = make_uint4(f2tf32(vf.x), f2tf32(vf.y), f2tf32(vf.z), f2tf32(vf.w));
        }
        __syncthreads();

        float s[8][4];
#pragma unroll
        for (int i = 0; i < 8; i++)
#pragma unroll
            for (int j = 0; j < 4; j++) s[i][j] = 0.f;
#pragma unroll
        for (int kk = 0; kk < 8; kk++) {
#pragma unroll
            for (int nt = 0; nt < 8; nt++) {
                uint32_t b[2];
                b[0] = Ks[nt * 8 + gid][kk * 8 + tig];
                b[1] = Ks[nt * 8 + gid][kk * 8 + tig + 4];
                mma8(s[nt], qa[kk], b);
            }
        }

        float mt0 = -1e30f, mt1 = -1e30f;
#pragma unroll
        for (int nt = 0; nt < 8; nt++) {
            mt0 = fmaxf(mt0, fmaxf(s[nt][0], s[nt][1]));
            mt1 = fmaxf(mt1, fmaxf(s[nt][2], s[nt][3]));
        }
        mt0 = fmaxf(mt0, __shfl_xor_sync(FULLMASK, mt0, 1));
        mt0 = fmaxf(mt0, __shfl_xor_sync(FULLMASK, mt0, 2));
        mt1 = fmaxf(mt1, __shfl_xor_sync(FULLMASK, mt1, 1));
        mt1 = fmaxf(mt1, __shfl_xor_sync(FULLMASK, mt1, 2));

        const float mn0 = fmaxf(m0, mt0), mn1 = fmaxf(m1, mt1);
        const float f0 = __expf(m0 - mn0), f1 = __expf(m1 - mn1);

        float rs0 = 0.f, rs1 = 0.f;
#pragma unroll
        for (int nt = 0; nt < 8; nt++) {
            s[nt][0] = __expf(s[nt][0] - mn0);
            s[nt][1] = __expf(s[nt][1] - mn0);
            s[nt][2] = __expf(s[nt][2] - mn1);
            s[nt][3] = __expf(s[nt][3] - mn1);
            rs0 += s[nt][0] + s[nt][1];
            rs1 += s[nt][2] + s[nt][3];
        }
        rs0 += __shfl_xor_sync(FULLMASK, rs0, 1);
        rs0 += __shfl_xor_sync(FULLMASK, rs0, 2);
        rs1 += __shfl_xor_sync(FULLMASK, rs1, 1);
        rs1 += __shfl_xor_sync(FULLMASK, rs1, 2);

        l0 = l0 * f0 + rs0;
        l1 = l1 * f1 + rs1;
        m0 = mn0;
        m1 = mn1;
#pragma unroll
        for (int nt = 0; nt < 8; nt++) {
            o[nt][0] *= f0; o[nt][1] *= f0;
            o[nt][2] *= f1; o[nt][3] *= f1;
        }

        const int src0 = (lane & ~3) | (tig >> 1);
        const int src1 = src0 + 2;
        const bool odd = tig & 1;
#pragma unroll
        for (int kt = 0; kt < 8; kt++) {
            const float v00 = __shfl_sync(FULLMASK, s[kt][0], src0);
            const float v01 = __shfl_sync(FULLMASK, s[kt][1], src0);
            const float v10 = __shfl_sync(FULLMASK, s[kt][2], src0);
            const float v11 = __shfl_sync(FULLMASK, s[kt][3], src0);
            const float u00 = __shfl_sync(FULLMASK, s[kt][0], src1);
            const float u01 = __shfl_sync(FULLMASK, s[kt][1], src1);
            const float u10 = __shfl_sync(FULLMASK, s[kt][2], src1);
            const float u11 = __shfl_sync(FULLMASK, s[kt][3], src1);
            uint32_t pa[4];
            pa[0] = f2tf32(odd ? v01 : v00);
            pa[1] = f2tf32(odd ? v11 : v10);
            pa[2] = f2tf32(odd ? u01 : u00);
            pa[3] = f2tf32(odd ? u11 : u10);
#pragma unroll
            for (int nt = 0; nt < 8; nt++) {
                uint32_t b[2];
                b[0] = Vs[kt * 8 + tig][nt * 8 + gid];
                b[1] = Vs[kt * 8 + tig + 4][nt * 8 + gid];
                mma8(o[nt], pa, b);
            }
        }
    }

    const float inv0 = 1.f / l0, inv1 = 1.f / l1;
    const int b = bh >> 4, h = bh & 15;
    const int n0 = qbase + w * 16 + gid;
    float* x0 = g_X + ((size_t)b * 2048 + n0) * 1024 + h * 64;
    float* x8 = x0 + 8 * 1024;
#pragma unroll
    for (int nt = 0; nt < 8; nt++) {
        const int d = nt * 8 + tig * 2;
        *(float2*)(x0 + d) = make_float2(o[nt][0] * inv0, o[nt][1] * inv0);
        *(float2*)(x8 + d) = make_float2(o[nt][2] * inv1, o[nt][3] * inv1);
    }
}

// ---------------------------------------------------------------------------
extern "C" void kernel_launch(void* const* d_in, const int* in_sizes, int n_in,
                              void* d_out, int out_size)
{
    const float* q     = (const float*)d_in[0];
    const float* k     = (const float*)d_in[1];
    const float* v     = (const float*)d_in[2];
    const float* Wqkv  = (const float*)d_in[3];
    const float* Wproj = (const float*)d_in[4];
    const float* bproj = (const float*)d_in[5];
    float* out = (float*)d_out;

    // 1) fused QKV projection -> g_Q/g_K/g_V (M=4096, N=3072, K=3072)
    gemm_tf32_nt<0><<<dim3(24, 32), 128>>>(q, k, v, Wqkv, nullptr, nullptr, 3072, 3072);
    // 2) flash attention -> g_X
    attn_flash<<<dim3(16, 32), 256>>>();
    // 3) output projection + bias -> d_out (M=4096, N=1024, K=1024)
    gemm_tf32_nt<1><<<dim3(8, 32), 128>>>(nullptr, nullptr, nullptr, Wproj, bproj, out, 1024, 1024);
}

// round 4
// speedup vs baseline: 2.4464x; 1.9829x over previous
#include <cuda_runtime.h>
#include <cuda_fp16.h>
#include <cstdint>

#define FULLMASK 0xffffffffu

// ---------------------------------------------------------------------------
// Device-global scratch (allocation-free rule). All fp16.
static __device__ __half g_Ah[4096 * 3072];   // concat [q|k|v]
static __device__ __half g_Wh[3072 * 3072];   // W_qkv
static __device__ __half g_Wph[1024 * 1024];  // W_proj
static __device__ __half g_Q[32 * 2048 * 64]; // [B*H, N, hd], scale folded in
static __device__ __half g_K[32 * 2048 * 64];
static __device__ __half g_V[32 * 2048 * 64];
static __device__ __half g_Xh[2 * 2048 * 1024];

__device__ __forceinline__ uint32_t smem_u32(const void* p) {
    uint32_t a;
    asm("{ .reg .u64 t; cvta.to.shared.u64 t, %1; cvt.u32.u64 %0, t; }"
        : "=r"(a) : "l"(p));
    return a;
}

#define CP_ASYNC16(dst, src) \
    asm volatile("cp.async.cg.shared.global [%0], [%1], 16;" :: "r"(dst), "l"(src))
#define CP_COMMIT() asm volatile("cp.async.commit_group;" ::: "memory")
#define CP_WAIT1()  asm volatile("cp.async.wait_group 1;"  ::: "memory")
#define CP_WAIT0()  asm volatile("cp.async.wait_group 0;"  ::: "memory")

__device__ __forceinline__ void mma16(float c[4], const uint32_t a[4], const uint32_t b[2]) {
    asm volatile(
        "mma.sync.aligned.m16n8k16.row.col.f32.f16.f16.f32 "
        "{%0,%1,%2,%3}, {%4,%5,%6,%7}, {%8,%9}, {%0,%1,%2,%3};"
        : "+f"(c[0]), "+f"(c[1]), "+f"(c[2]), "+f"(c[3])
        : "r"(a[0]), "r"(a[1]), "r"(a[2]), "r"(a[3]), "r"(b[0]), "r"(b[1]));
}

__device__ __forceinline__ uint32_t pack_h2(float lo, float hi) {
    __half2 h = __floats2half2_rn(lo, hi);
    return *reinterpret_cast<uint32_t*>(&h);
}

// ---------------------------------------------------------------------------
// Prepass: fp32 -> fp16 conversions (done once; GEMMs re-read these 24-32x).
// ---------------------------------------------------------------------------
__global__ void cvt_A(const float* __restrict__ q, const float* __restrict__ k,
                      const float* __restrict__ v) {
    for (int i4 = (blockIdx.x * blockDim.x + threadIdx.x) * 4; i4 < 4096 * 3072;
         i4 += gridDim.x * blockDim.x * 4) {
        const int r = i4 / 3072;
        const int c = i4 - r * 3072;
        const float* s = ((c < 1024) ? q : ((c < 2048) ? k : v)) + (size_t)r * 1024 + (c & 1023);
        const float4 f = *(const float4*)s;
        __half2* d = (__half2*)&g_Ah[(size_t)r * 3072 + c];
        d[0] = __floats2half2_rn(f.x, f.y);
        d[1] = __floats2half2_rn(f.z, f.w);
    }
}

__global__ void cvt_Wqkv(const float* __restrict__ W) {
    for (int i4 = (blockIdx.x * blockDim.x + threadIdx.x) * 4; i4 < 3072 * 3072;
         i4 += gridDim.x * blockDim.x * 4) {
        const float4 f = *(const float4*)(W + i4);
        __half2* d = (__half2*)&g_Wh[i4];
        d[0] = __floats2half2_rn(f.x, f.y);
        d[1] = __floats2half2_rn(f.z, f.w);
    }
}

__global__ void cvt_Wp(const float* __restrict__ W) {
    for (int i4 = (blockIdx.x * blockDim.x + threadIdx.x) * 4; i4 < 1024 * 1024;
         i4 += gridDim.x * blockDim.x * 4) {
        const float4 f = *(const float4*)(W + i4);
        __half2* d = (__half2*)&g_Wph[i4];
        d[0] = __floats2half2_rn(f.x, f.y);
        d[1] = __floats2half2_rn(f.z, f.w);
    }
}

// ---------------------------------------------------------------------------
// fp16 NT GEMM: C[m,j] = sum_k A[m,k] * W[j,k], fp32 accumulate.
// Block 128x128, BK=32, 128 threads (4 warps 2x2), warp tile 64x64.
// 3-stage cp.async pipeline, padded smem rows (40 halfs) -> conflict-free.
// MODE 0: A=g_Ah, B=g_Wh, scatter fp16 to g_Q/g_K/g_V (Q scaled by 0.125).
// MODE 1: A=g_Xh, B=g_Wph, out = C + bias (fp32).
// ---------------------------------------------------------------------------
template <int MODE>
__global__ void __launch_bounds__(128) gemm_h(const float* __restrict__ bias,
                                              float* __restrict__ out)
{
    constexpr int KDIM = (MODE == 0) ? 3072 : 1024;
    constexpr int NK   = KDIM / 32;
    // stage: A tile 128 rows x 32 halfs, padded to 40 halfs (80B) = 10240B; B same.
    constexpr int STAGE_BYTES = 20480;

    extern __shared__ __align__(16) char sm[];
    const uint32_t sbase = smem_u32(sm);

    const __half* __restrict__ A = (MODE == 0) ? g_Ah : g_Xh;
    const __half* __restrict__ B = (MODE == 0) ? g_Wh : g_Wph;

    const int tid  = threadIdx.x;
    const int lane = tid & 31;
    const int w    = tid >> 5;
    const int gid  = lane >> 2;
    const int tig  = lane & 3;
    const int warp_m = (w >> 1) * 64;
    const int warp_n = (w & 1) * 64;
    const int mBase  = blockIdx.y * 128;
    const int nBase  = blockIdx.x * 128;

    auto stage = [&](int kt, int st) {
#pragma unroll
        for (int i = 0; i < 8; i++) {
            const int c   = tid + 128 * i;
            const int mat = c >> 9;          // 0=A (i<4), 1=B (i>=4)
            const int cc  = c & 511;
            const int row = cc >> 2;
            const int ch  = cc & 3;
            const __half* src = (mat == 0)
                ? (A + (size_t)(mBase + row) * KDIM + kt * 32 + ch * 8)
                : (B + (size_t)(nBase + row) * KDIM + kt * 32 + ch * 8);
            const uint32_t dst = sbase + st * STAGE_BYTES + mat * 10240 + row * 80 + ch * 16;
            CP_ASYNC16(dst, src);
        }
        CP_COMMIT();
    };

    float acc[4][8][4];
#pragma unroll
    for (int i = 0; i < 4; i++)
#pragma unroll
        for (int j = 0; j < 8; j++)
#pragma unroll
            for (int e = 0; e < 4; e++) acc[i][j][e] = 0.f;

    stage(0, 0);
    stage(1, 1);

    for (int kt = 0; kt < NK; kt++) {
        const int st = kt % 3;
        if (kt + 1 < NK) { CP_WAIT1(); } else { CP_WAIT0(); }
        __syncthreads();
        if (kt + 2 < NK) stage(kt + 2, (kt + 2) % 3);  // overwrites buf (kt-1): done pre-sync

        const __half* Ash = (const __half*)(sm + st * STAGE_BYTES);
        const __half* Bsh = (const __half*)(sm + st * STAGE_BYTES + 10240);

#pragma unroll
        for (int ks = 0; ks < 2; ks++) {
            uint32_t a[4][4], b[8][2];
#pragma unroll
            for (int mt = 0; mt < 4; mt++) {
                const __half* ar = Ash + (warp_m + mt * 16 + gid) * 40 + ks * 16 + 2 * tig;
                a[mt][0] = *(const uint32_t*)ar;
                a[mt][1] = *(const uint32_t*)(ar + 8 * 40);
                a[mt][2] = *(const uint32_t*)(ar + 8);
                a[mt][3] = *(const uint32_t*)(ar + 8 * 40 + 8);
            }
#pragma unroll
            for (int nt = 0; nt < 8; nt++) {
                const __half* br = Bsh + (warp_n + nt * 8 + gid) * 40 + ks * 16 + 2 * tig;
                b[nt][0] = *(const uint32_t*)br;
                b[nt][1] = *(const uint32_t*)(br + 8);
            }
#pragma unroll
            for (int mt = 0; mt < 4; mt++)
#pragma unroll
                for (int nt = 0; nt < 8; nt++)
                    mma16(acc[mt][nt], a[mt], b[nt]);
        }
    }

    // Epilogue. C frag: c0(row g, col 2t), c1(g, 2t+1), c2(g+8, 2t), c3(g+8, 2t+1).
#pragma unroll
    for (int mt = 0; mt < 4; mt++) {
        const int row0 = mBase + warp_m + mt * 16 + gid;
#pragma unroll
        for (int nt = 0; nt < 8; nt++) {
            const int col = nBase + warp_n + nt * 8 + 2 * tig;
            if (MODE == 0) {
                const int t = col >> 10, hh = (col >> 6) & 15, d = col & 63;
                const float sc = (t == 0) ? 0.125f : 1.f;
                __half* dst = ((t == 0) ? g_Q : ((t == 1) ? g_K : g_V)) +
                    ((size_t)((row0 >> 11) * 16 + hh) * 2048 + (row0 & 2047)) * 64 + d;
                *(__half2*)dst =
                    __floats2half2_rn(acc[mt][nt][0] * sc, acc[mt][nt][1] * sc);
                *(__half2*)(dst + 8 * 64) =
                    __floats2half2_rn(acc[mt][nt][2] * sc, acc[mt][nt][3] * sc);
            } else {
                const float b0 = bias[col], b1 = bias[col + 1];
                *(float2*)(out + (size_t)row0 * 1024 + col) =
                    make_float2(acc[mt][nt][0] + b0, acc[mt][nt][1] + b1);
                *(float2*)(out + (size_t)(row0 + 8) * 1024 + col) =
                    make_float2(acc[mt][nt][2] + b0, acc[mt][nt][3] + b1);
            }
        }
    }
}

// ---------------------------------------------------------------------------
// fp16 flash attention: grid (16, 32), 256 threads (8 warps, 16 q-rows each).
// K/V tiles (64 kv rows) via 3-stage cp.async. S C-frag == PV A-frag (no shuffles).
// V B-frags via ldmatrix.x2.trans. Output fp16 to g_Xh.
// ---------------------------------------------------------------------------
__global__ void __launch_bounds__(256) attn_flash_h()
{
    // stage: K 64 rows x 64 halfs padded to 72 (144B) = 9216B; V same. 3 stages.
    constexpr int KV_BYTES = 9216;
    constexpr int STAGE_BYTES = 2 * KV_BYTES;
    extern __shared__ __align__(16) char sm[];
    const uint32_t sbase = smem_u32(sm);

    const int bh    = blockIdx.y;
    const int qbase = blockIdx.x * 128;
    const int tid   = threadIdx.x;
    const int lane  = tid & 31;
    const int w     = tid >> 5;
    const int gid   = lane >> 2;
    const int tig   = lane & 3;

    const __half* Kp = g_K + (size_t)bh * (2048 * 64);
    const __half* Vp = g_V + (size_t)bh * (2048 * 64);

    auto stage = [&](int kv_tile, int st) {
#pragma unroll
        for (int i = 0; i < 4; i++) {
            const int c   = tid + 256 * i;
            const int mat = c >> 9;          // 0=K, 1=V
            const int cc  = c & 511;
            const int row = cc >> 3;
            const int ch  = cc & 7;
            const __half* src = ((mat == 0) ? Kp : Vp) +
                (size_t)(kv_tile * 64 + row) * 64 + ch * 8;
            const uint32_t dst = sbase + st * STAGE_BYTES + mat * KV_BYTES + row * 144 + ch * 16;
            CP_ASYNC16(dst, src);
        }
        CP_COMMIT();
    };

    // Q fragments (scale pre-folded at QKV epilogue): 4 k-steps x 4 regs.
    uint32_t qa[4][4];
    {
        const __half* q0 = g_Q + ((size_t)bh * 2048 + qbase + w * 16 + gid) * 64;
#pragma unroll
        for (int s = 0; s < 4; s++) {
            qa[s][0] = *(const uint32_t*)(q0 + s * 16 + 2 * tig);
            qa[s][1] = *(const uint32_t*)(q0 + 8 * 64 + s * 16 + 2 * tig);
            qa[s][2] = *(const uint32_t*)(q0 + s * 16 + 2 * tig + 8);
            qa[s][3] = *(const uint32_t*)(q0 + 8 * 64 + s * 16 + 2 * tig + 8);
        }
    }

    float o[8][4];
#pragma unroll
    for (int i = 0; i < 8; i++)
#pragma unroll
        for (int j = 0; j < 4; j++) o[i][j] = 0.f;
    float m0 = -1e30f, m1 = -1e30f, l0 = 0.f, l1 = 0.f;

    stage(0, 0);
    stage(1, 1);

    for (int it = 0; it < 32; it++) {
        const int st = it % 3;
        if (it + 1 < 32) { CP_WAIT1(); } else { CP_WAIT0(); }
        __syncthreads();
        if (it + 2 < 32) stage(it + 2, (it + 2) % 3);

        const __half* Ksh = (const __half*)(sm + st * STAGE_BYTES);
        const uint32_t vsb = sbase + st * STAGE_BYTES + KV_BYTES;

        // S = Q K^T (16 x 64 per warp), fp32 accum
        float s[8][4];
#pragma unroll
        for (int i = 0; i < 8; i++)
#pragma unroll
            for (int j = 0; j < 4; j++) s[i][j] = 0.f;
#pragma unroll
        for (int ks = 0; ks < 4; ks++) {
#pragma unroll
            for (int nt = 0; nt < 8; nt++) {
                const __half* br = Ksh + (nt * 8 + gid) * 72 + ks * 16 + 2 * tig;
                uint32_t b[2];
                b[0] = *(const uint32_t*)br;
                b[1] = *(const uint32_t*)(br + 8);
                mma16(s[nt], qa[ks], b);
            }
        }

        // Online softmax (rows gid / gid+8; stats shared across the 4-lane quad).
        float mt0 = -1e30f, mt1 = -1e30f;
#pragma unroll
        for (int nt = 0; nt < 8; nt++) {
            mt0 = fmaxf(mt0, fmaxf(s[nt][0], s[nt][1]));
            mt1 = fmaxf(mt1, fmaxf(s[nt][2], s[nt][3]));
        }
        mt0 = fmaxf(mt0, __shfl_xor_sync(FULLMASK, mt0, 1));
        mt0 = fmaxf(mt0, __shfl_xor_sync(FULLMASK, mt0, 2));
        mt1 = fmaxf(mt1, __shfl_xor_sync(FULLMASK, mt1, 1));
        mt1 = fmaxf(mt1, __shfl_xor_sync(FULLMASK, mt1, 2));

        const float mn0 = fmaxf(m0, mt0), mn1 = fmaxf(m1, mt1);
        const float f0 = __expf(m0 - mn0), f1 = __expf(m1 - mn1);

        float rs0 = 0.f, rs1 = 0.f;
#pragma unroll
        for (int nt = 0; nt < 8; nt++) {
            s[nt][0] = __expf(s[nt][0] - mn0);
            s[nt][1] = __expf(s[nt][1] - mn0);
            s[nt][2] = __expf(s[nt][2] - mn1);
            s[nt][3] = __expf(s[nt][3] - mn1);
            rs0 += s[nt][0] + s[nt][1];
            rs1 += s[nt][2] + s[nt][3];
        }
        rs0 += __shfl_xor_sync(FULLMASK, rs0, 1);
        rs0 += __shfl_xor_sync(FULLMASK, rs0, 2);
        rs1 += __shfl_xor_sync(FULLMASK, rs1, 1);
        rs1 += __shfl_xor_sync(FULLMASK, rs1, 2);

        l0 = l0 * f0 + rs0;
        l1 = l1 * f1 + rs1;
        m0 = mn0;
        m1 = mn1;
#pragma unroll
        for (int nt = 0; nt < 8; nt++) {
            o[nt][0] *= f0; o[nt][1] *= f0;
            o[nt][2] *= f1; o[nt][3] *= f1;
        }

        // O += P V. fp16 S C-frag IS the PV A-frag after half2 packing.
#pragma unroll
        for (int kt = 0; kt < 4; kt++) {
            uint32_t pa[4];
            pa[0] = pack_h2(s[2 * kt][0],     s[2 * kt][1]);      // (gid,   k=2tig)
            pa[1] = pack_h2(s[2 * kt][2],     s[2 * kt][3]);      // (gid+8, k=2tig)
            pa[2] = pack_h2(s[2 * kt + 1][0], s[2 * kt + 1][1]);  // (gid,   k=2tig+8)
            pa[3] = pack_h2(s[2 * kt + 1][2], s[2 * kt + 1][3]);  // (gid+8, k=2tig+8)
#pragma unroll
            for (int nt = 0; nt < 8; nt++) {
                // V B-frag via ldmatrix.x2.trans: rows kv kt*16+(lane&15), col d=nt*8
                const uint32_t addr = vsb + (kt * 16 + (lane & 15)) * 144 + nt * 16;
                uint32_t b0, b1;
                asm volatile(
                    "ldmatrix.sync.aligned.m8n8.x2.trans.shared.b16 {%0,%1}, [%2];"
                    : "=r"(b0), "=r"(b1) : "r"(addr));
                uint32_t b[2] = {b0, b1};
                mma16(o[nt], pa, b);
            }
        }
    }

    // Normalize, write fp16 to g_Xh[b, n, h*64 + d].
    const float inv0 = 1.f / l0, inv1 = 1.f / l1;
    const int b = bh >> 4, h = bh & 15;
    const int n0 = qbase + w * 16 + gid;
    __half* x0 = g_Xh + ((size_t)b * 2048 + n0) * 1024 + h * 64;
    __half* x8 = x0 + 8 * 1024;
#pragma unroll
    for (int nt = 0; nt < 8; nt++) {
        const int d = nt * 8 + 2 * tig;
        *(__half2*)(x0 + d) = __floats2half2_rn(o[nt][0] * inv0, o[nt][1] * inv0);
        *(__half2*)(x8 + d) = __floats2half2_rn(o[nt][2] * inv1, o[nt][3] * inv1);
    }
}

// ---------------------------------------------------------------------------
extern "C" void kernel_launch(void* const* d_in, const int* in_sizes, int n_in,
                              void* d_out, int out_size)
{
    const float* q     = (const float*)d_in[0];
    const float* k     = (const float*)d_in[1];
    const float* v     = (const float*)d_in[2];
    const float* Wqkv  = (const float*)d_in[3];
    const float* Wproj = (const float*)d_in[4];
    const float* bproj = (const float*)d_in[5];
    float* out = (float*)d_out;

    static bool attr_done = false;
    const int GEMM_SMEM = 3 * 20480;   // 61440
    const int ATTN_SMEM = 3 * 18432;   // 55296
    if (!attr_done) {
        cudaFuncSetAttribute(gemm_h<0>, cudaFuncAttributeMaxDynamicSharedMemorySize, GEMM_SMEM);
        cudaFuncSetAttribute(gemm_h<1>, cudaFuncAttributeMaxDynamicSharedMemorySize, GEMM_SMEM);
        cudaFuncSetAttribute(attn_flash_h, cudaFuncAttributeMaxDynamicSharedMemorySize, ATTN_SMEM);
        attr_done = true;
    }

    // 0) fp32 -> fp16 prepass (A concat, W_qkv, W_proj)
    cvt_A<<<2048, 256>>>(q, k, v);
    cvt_Wqkv<<<2048, 256>>>(Wqkv);
    cvt_Wp<<<512, 256>>>(Wproj);
    // 1) fused QKV projection -> g_Q/g_K/g_V (fp16, Q pre-scaled)
    gemm_h<0><<<dim3(24, 32), 128, GEMM_SMEM>>>(nullptr, nullptr);
    // 2) flash attention -> g_Xh (fp16)
    attn_flash_h<<<dim3(16, 32), 256, ATTN_SMEM>>>();
    // 3) output projection + bias -> d_out (fp32)
    gemm_h<1><<<dim3(8, 32), 128, GEMM_SMEM>>>(bproj, out);
}

// round 5
// speedup vs baseline: 2.4754x; 1.0119x over previous
#include <cuda_runtime.h>
#include <cuda_fp16.h>
#include <cstdint>

#define FULLMASK 0xffffffffu

// ---------------------------------------------------------------------------
// Device-global scratch (allocation-free rule). All fp16.
static __device__ __half g_Ah[4096 * 3072];   // concat [q|k|v]
static __device__ __half g_Wh[3072 * 3072];   // W_qkv
static __device__ __half g_Wph[1024 * 1024];  // W_proj
static __device__ __half g_Q[32 * 2048 * 64]; // [B*H, N, hd], scale folded in
static __device__ __half g_K[32 * 2048 * 64];
static __device__ __half g_V[32 * 2048 * 64];
static __device__ __half g_Xh[2 * 2048 * 1024];

__device__ __forceinline__ uint32_t smem_u32(const void* p) {
    uint32_t a;
    asm("{ .reg .u64 t; cvta.to.shared.u64 t, %1; cvt.u32.u64 %0, t; }"
        : "=r"(a) : "l"(p));
    return a;
}

#define CP_ASYNC16(dst, src) \
    asm volatile("cp.async.cg.shared.global [%0], [%1], 16;" :: "r"(dst), "l"(src))
#define CP_COMMIT() asm volatile("cp.async.commit_group;" ::: "memory")
#define CP_WAIT1()  asm volatile("cp.async.wait_group 1;"  ::: "memory")
#define CP_WAIT0()  asm volatile("cp.async.wait_group 0;"  ::: "memory")

__device__ __forceinline__ void mma16(float c[4], const uint32_t a[4], const uint32_t b[2]) {
    asm volatile(
        "mma.sync.aligned.m16n8k16.row.col.f32.f16.f16.f32 "
        "{%0,%1,%2,%3}, {%4,%5,%6,%7}, {%8,%9}, {%0,%1,%2,%3};"
        : "+f"(c[0]), "+f"(c[1]), "+f"(c[2]), "+f"(c[3])
        : "r"(a[0]), "r"(a[1]), "r"(a[2]), "r"(a[3]), "r"(b[0]), "r"(b[1]));
}

__device__ __forceinline__ uint32_t pack_h2(float lo, float hi) {
    __half2 h = __floats2half2_rn(lo, hi);
    return *reinterpret_cast<uint32_t*>(&h);
}

// ---------------------------------------------------------------------------
// Prepass: fp32 -> fp16 conversions (done once; GEMMs re-read these 24-32x).
// ---------------------------------------------------------------------------
__global__ void cvt_A(const float* __restrict__ q, const float* __restrict__ k,
                      const float* __restrict__ v) {
    for (int i4 = (blockIdx.x * blockDim.x + threadIdx.x) * 4; i4 < 4096 * 3072;
         i4 += gridDim.x * blockDim.x * 4) {
        const int r = i4 / 3072;
        const int c = i4 - r * 3072;
        const float* s = ((c < 1024) ? q : ((c < 2048) ? k : v)) + (size_t)r * 1024 + (c & 1023);
        const float4 f = *(const float4*)s;
        __half2* d = (__half2*)&g_Ah[(size_t)r * 3072 + c];
        d[0] = __floats2half2_rn(f.x, f.y);
        d[1] = __floats2half2_rn(f.z, f.w);
    }
}

__global__ void cvt_Wqkv(const float* __restrict__ W) {
    for (int i4 = (blockIdx.x * blockDim.x + threadIdx.x) * 4; i4 < 3072 * 3072;
         i4 += gridDim.x * blockDim.x * 4) {
        const float4 f = *(const float4*)(W + i4);
        __half2* d = (__half2*)&g_Wh[i4];
        d[0] = __floats2half2_rn(f.x, f.y);
        d[1] = __floats2half2_rn(f.z, f.w);
    }
}

__global__ void cvt_Wp(const float* __restrict__ W) {
    for (int i4 = (blockIdx.x * blockDim.x + threadIdx.x) * 4; i4 < 1024 * 1024;
         i4 += gridDim.x * blockDim.x * 4) {
        const float4 f = *(const float4*)(W + i4);
        __half2* d = (__half2*)&g_Wph[i4];
        d[0] = __floats2half2_rn(f.x, f.y);
        d[1] = __floats2half2_rn(f.z, f.w);
    }
}

// ---------------------------------------------------------------------------
// fp16 NT GEMM: C[m,j] = sum_k A[m,k] * W[j,k], fp32 accumulate.
// Block 128x128, BK=32, 256 threads (8 warps 4m x 2n), warp tile 32x64.
// __launch_bounds__(256,2) -> <=128 regs -> 2 CTAs/SM = 16 warps (latency fix).
// 3-stage cp.async pipeline, padded smem rows (40 halfs) -> conflict-free.
// MODE 0: A=g_Ah, B=g_Wh, scatter fp16 to g_Q/g_K/g_V (Q scaled by 0.125).
// MODE 1: A=g_Xh, B=g_Wph, out = C + bias (fp32).
// ---------------------------------------------------------------------------
template <int MODE>
__global__ void __launch_bounds__(256, 2) gemm_h(const float* __restrict__ bias,
                                                 float* __restrict__ out)
{
    constexpr int KDIM = (MODE == 0) ? 3072 : 1024;
    constexpr int NK   = KDIM / 32;
    // stage: A tile 128 rows x 32 halfs, padded to 40 halfs (80B) = 10240B; B same.
    constexpr int STAGE_BYTES = 20480;

    extern __shared__ __align__(16) char sm[];
    const uint32_t sbase = smem_u32(sm);

    const __half* __restrict__ A = (MODE == 0) ? g_Ah : g_Xh;
    const __half* __restrict__ B = (MODE == 0) ? g_Wh : g_Wph;

    const int tid  = threadIdx.x;
    const int lane = tid & 31;
    const int w    = tid >> 5;
    const int gid  = lane >> 2;
    const int tig  = lane & 3;
    const int warp_m = (w >> 1) * 32;   // 4 m-warps
    const int warp_n = (w & 1) * 64;    // 2 n-warps
    const int mBase  = blockIdx.y * 128;
    const int nBase  = blockIdx.x * 128;

    auto stage = [&](int kt, int st) {
#pragma unroll
        for (int i = 0; i < 4; i++) {
            const int c   = tid + 256 * i;
            const int mat = c >> 9;          // 0=A, 1=B
            const int cc  = c & 511;
            const int row = cc >> 2;
            const int ch  = cc & 3;
            const __half* src = (mat == 0)
                ? (A + (size_t)(mBase + row) * KDIM + kt * 32 + ch * 8)
                : (B + (size_t)(nBase + row) * KDIM + kt * 32 + ch * 8);
            const uint32_t dst = sbase + st * STAGE_BYTES + mat * 10240 + row * 80 + ch * 16;
            CP_ASYNC16(dst, src);
        }
        CP_COMMIT();
    };

    float acc[2][8][4];
#pragma unroll
    for (int i = 0; i < 2; i++)
#pragma unroll
        for (int j = 0; j < 8; j++)
#pragma unroll
            for (int e = 0; e < 4; e++) acc[i][j][e] = 0.f;

    stage(0, 0);
    stage(1, 1);

    for (int kt = 0; kt < NK; kt++) {
        const int st = kt % 3;
        if (kt + 1 < NK) { CP_WAIT1(); } else { CP_WAIT0(); }
        __syncthreads();
        if (kt + 2 < NK) stage(kt + 2, (kt + 2) % 3);  // buf (kt-1): released pre-sync

        const __half* Ash = (const __half*)(sm + st * STAGE_BYTES);
        const __half* Bsh = (const __half*)(sm + st * STAGE_BYTES + 10240);

#pragma unroll
        for (int ks = 0; ks < 2; ks++) {
            uint32_t a[2][4], b[8][2];
#pragma unroll
            for (int mt = 0; mt < 2; mt++) {
                const __half* ar = Ash + (warp_m + mt * 16 + gid) * 40 + ks * 16 + 2 * tig;
                a[mt][0] = *(const uint32_t*)ar;
                a[mt][1] = *(const uint32_t*)(ar + 8 * 40);
                a[mt][2] = *(const uint32_t*)(ar + 8);
                a[mt][3] = *(const uint32_t*)(ar + 8 * 40 + 8);
            }
#pragma unroll
            for (int nt = 0; nt < 8; nt++) {
                const __half* br = Bsh + (warp_n + nt * 8 + gid) * 40 + ks * 16 + 2 * tig;
                b[nt][0] = *(const uint32_t*)br;
                b[nt][1] = *(const uint32_t*)(br + 8);
            }
#pragma unroll
            for (int mt = 0; mt < 2; mt++)
#pragma unroll
                for (int nt = 0; nt < 8; nt++)
                    mma16(acc[mt][nt], a[mt], b[nt]);
        }
    }

    // Epilogue. C frag: c0(row g, col 2t), c1(g, 2t+1), c2(g+8, 2t), c3(g+8, 2t+1).
#pragma unroll
    for (int mt = 0; mt < 2; mt++) {
        const int row0 = mBase + warp_m + mt * 16 + gid;
#pragma unroll
        for (int nt = 0; nt < 8; nt++) {
            const int col = nBase + warp_n + nt * 8 + 2 * tig;
            if (MODE == 0) {
                const int t = col >> 10, hh = (col >> 6) & 15, d = col & 63;
                const float sc = (t == 0) ? 0.125f : 1.f;
                __half* dst = ((t == 0) ? g_Q : ((t == 1) ? g_K : g_V)) +
                    ((size_t)((row0 >> 11) * 16 + hh) * 2048 + (row0 & 2047)) * 64 + d;
                *(__half2*)dst =
                    __floats2half2_rn(acc[mt][nt][0] * sc, acc[mt][nt][1] * sc);
                *(__half2*)(dst + 8 * 64) =
                    __floats2half2_rn(acc[mt][nt][2] * sc, acc[mt][nt][3] * sc);
            } else {
                const float b0 = bias[col], b1 = bias[col + 1];
                *(float2*)(out + (size_t)row0 * 1024 + col) =
                    make_float2(acc[mt][nt][0] + b0, acc[mt][nt][1] + b1);
                *(float2*)(out + (size_t)(row0 + 8) * 1024 + col) =
                    make_float2(acc[mt][nt][2] + b0, acc[mt][nt][3] + b1);
            }
        }
    }
}

// ---------------------------------------------------------------------------
// fp16 flash attention (unchanged from R4): grid (16, 32), 256 threads.
// ---------------------------------------------------------------------------
__global__ void __launch_bounds__(256) attn_flash_h()
{
    constexpr int KV_BYTES = 9216;
    constexpr int STAGE_BYTES = 2 * KV_BYTES;
    extern __shared__ __align__(16) char sm[];
    const uint32_t sbase = smem_u32(sm);

    const int bh    = blockIdx.y;
    const int qbase = blockIdx.x * 128;
    const int tid   = threadIdx.x;
    const int lane  = tid & 31;
    const int w     = tid >> 5;
    const int gid   = lane >> 2;
    const int tig   = lane & 3;

    const __half* Kp = g_K + (size_t)bh * (2048 * 64);
    const __half* Vp = g_V + (size_t)bh * (2048 * 64);

    auto stage = [&](int kv_tile, int st) {
#pragma unroll
        for (int i = 0; i < 4; i++) {
            const int c   = tid + 256 * i;
            const int mat = c >> 9;          // 0=K, 1=V
            const int cc  = c & 511;
            const int row = cc >> 3;
            const int ch  = cc & 7;
            const __half* src = ((mat == 0) ? Kp : Vp) +
                (size_t)(kv_tile * 64 + row) * 64 + ch * 8;
            const uint32_t dst = sbase + st * STAGE_BYTES + mat * KV_BYTES + row * 144 + ch * 16;
            CP_ASYNC16(dst, src);
        }
        CP_COMMIT();
    };

    uint32_t qa[4][4];
    {
        const __half* q0 = g_Q + ((size_t)bh * 2048 + qbase + w * 16 + gid) * 64;
#pragma unroll
        for (int s = 0; s < 4; s++) {
            qa[s][0] = *(const uint32_t*)(q0 + s * 16 + 2 * tig);
            qa[s][1] = *(const uint32_t*)(q0 + 8 * 64 + s * 16 + 2 * tig);
            qa[s][2] = *(const uint32_t*)(q0 + s * 16 + 2 * tig + 8);
            qa[s][3] = *(const uint32_t*)(q0 + 8 * 64 + s * 16 + 2 * tig + 8);
        }
    }

    float o[8][4];
#pragma unroll
    for (int i = 0; i < 8; i++)
#pragma unroll
        for (int j = 0; j < 4; j++) o[i][j] = 0.f;
    float m0 = -1e30f, m1 = -1e30f, l0 = 0.f, l1 = 0.f;

    stage(0, 0);
    stage(1, 1);

    for (int it = 0; it < 32; it++) {
        const int st = it % 3;
        if (it + 1 < 32) { CP_WAIT1(); } else { CP_WAIT0(); }
        __syncthreads();
        if (it + 2 < 32) stage(it + 2, (it + 2) % 3);

        const __half* Ksh = (const __half*)(sm + st * STAGE_BYTES);
        const uint32_t vsb = sbase + st * STAGE_BYTES + KV_BYTES;

        float s[8][4];
#pragma unroll
        for (int i = 0; i < 8; i++)
#pragma unroll
            for (int j = 0; j < 4; j++) s[i][j] = 0.f;
#pragma unroll
        for (int ks = 0; ks < 4; ks++) {
#pragma unroll
            for (int nt = 0; nt < 8; nt++) {
                const __half* br = Ksh + (nt * 8 + gid) * 72 + ks * 16 + 2 * tig;
                uint32_t b[2];
                b[0] = *(const uint32_t*)br;
                b[1] = *(const uint32_t*)(br + 8);
                mma16(s[nt], qa[ks], b);
            }
        }

        float mt0 = -1e30f, mt1 = -1e30f;
#pragma unroll
        for (int nt = 0; nt < 8; nt++) {
            mt0 = fmaxf(mt0, fmaxf(s[nt][0], s[nt][1]));
            mt1 = fmaxf(mt1, fmaxf(s[nt][2], s[nt][3]));
        }
        mt0 = fmaxf(mt0, __shfl_xor_sync(FULLMASK, mt0, 1));
        mt0 = fmaxf(mt0, __shfl_xor_sync(FULLMASK, mt0, 2));
        mt1 = fmaxf(mt1, __shfl_xor_sync(FULLMASK, mt1, 1));
        mt1 = fmaxf(mt1, __shfl_xor_sync(FULLMASK, mt1, 2));

        const float mn0 = fmaxf(m0, mt0), mn1 = fmaxf(m1, mt1);
        const float f0 = __expf(m0 - mn0), f1 = __expf(m1 - mn1);

        float rs0 = 0.f, rs1 = 0.f;
#pragma unroll
        for (int nt = 0; nt < 8; nt++) {
            s[nt][0] = __expf(s[nt][0] - mn0);
            s[nt][1] = __expf(s[nt][1] - mn0);
            s[nt][2] = __expf(s[nt][2] - mn1);
            s[nt][3] = __expf(s[nt][3] - mn1);
            rs0 += s[nt][0] + s[nt][1];
            rs1 += s[nt][2] + s[nt][3];
        }
        rs0 += __shfl_xor_sync(FULLMASK, rs0, 1);
        rs0 += __shfl_xor_sync(FULLMASK, rs0, 2);
        rs1 += __shfl_xor_sync(FULLMASK, rs1, 1);
        rs1 += __shfl_xor_sync(FULLMASK, rs1, 2);

        l0 = l0 * f0 + rs0;
        l1 = l1 * f1 + rs1;
        m0 = mn0;
        m1 = mn1;
#pragma unroll
        for (int nt = 0; nt < 8; nt++) {
            o[nt][0] *= f0; o[nt][1] *= f0;
            o[nt][2] *= f1; o[nt][3] *= f1;
        }

#pragma unroll
        for (int kt = 0; kt < 4; kt++) {
            uint32_t pa[4];
            pa[0] = pack_h2(s[2 * kt][0],     s[2 * kt][1]);
            pa[1] = pack_h2(s[2 * kt][2],     s[2 * kt][3]);
            pa[2] = pack_h2(s[2 * kt + 1][0], s[2 * kt + 1][1]);
            pa[3] = pack_h2(s[2 * kt + 1][2], s[2 * kt + 1][3]);
#pragma unroll
            for (int nt = 0; nt < 8; nt++) {
                const uint32_t addr = vsb + (kt * 16 + (lane & 15)) * 144 + nt * 16;
                uint32_t b0, b1;
                asm volatile(
                    "ldmatrix.sync.aligned.m8n8.x2.trans.shared.b16 {%0,%1}, [%2];"
                    : "=r"(b0), "=r"(b1) : "r"(addr));
                uint32_t b[2] = {b0, b1};
                mma16(o[nt], pa, b);
            }
        }
    }

    const float inv0 = 1.f / l0, inv1 = 1.f / l1;
    const int b = bh >> 4, h = bh & 15;
    const int n0 = qbase + w * 16 + gid;
    __half* x0 = g_Xh + ((size_t)b * 2048 + n0) * 1024 + h * 64;
    __half* x8 = x0 + 8 * 1024;
#pragma unroll
    for (int nt = 0; nt < 8; nt++) {
        const int d = nt * 8 + 2 * tig;
        *(__half2*)(x0 + d) = __floats2half2_rn(o[nt][0] * inv0, o[nt][1] * inv0);
        *(__half2*)(x8 + d) = __floats2half2_rn(o[nt][2] * inv1, o[nt][3] * inv1);
    }
}

// ---------------------------------------------------------------------------
extern "C" void kernel_launch(void* const* d_in, const int* in_sizes, int n_in,
                              void* d_out, int out_size)
{
    const float* q     = (const float*)d_in[0];
    const float* k     = (const float*)d_in[1];
    const float* v     = (const float*)d_in[2];
    const float* Wqkv  = (const float*)d_in[3];
    const float* Wproj = (const float*)d_in[4];
    const float* bproj = (const float*)d_in[5];
    float* out = (float*)d_out;

    static bool attr_done = false;
    const int GEMM_SMEM = 3 * 20480;   // 61440
    const int ATTN_SMEM = 3 * 18432;   // 55296
    if (!attr_done) {
        cudaFuncSetAttribute(gemm_h<0>, cudaFuncAttributeMaxDynamicSharedMemorySize, GEMM_SMEM);
        cudaFuncSetAttribute(gemm_h<1>, cudaFuncAttributeMaxDynamicSharedMemorySize, GEMM_SMEM);
        cudaFuncSetAttribute(attn_flash_h, cudaFuncAttributeMaxDynamicSharedMemorySize, ATTN_SMEM);
        attr_done = true;
    }

    // 0) fp32 -> fp16 prepass
    cvt_A<<<2048, 256>>>(q, k, v);
    cvt_Wqkv<<<2048, 256>>>(Wqkv);
    cvt_Wp<<<512, 256>>>(Wproj);
    // 1) fused QKV projection -> g_Q/g_K/g_V (fp16, Q pre-scaled)
    gemm_h<0><<<dim3(24, 32), 256, GEMM_SMEM>>>(nullptr, nullptr);
    // 2) flash attention -> g_Xh (fp16)
    attn_flash_h<<<dim3(16, 32), 256, ATTN_SMEM>>>();
    // 3) output projection + bias -> d_out (fp32)
    gemm_h<1><<<dim3(8, 32), 256, GEMM_SMEM>>>(bproj, out);
}

// round 6
// speedup vs baseline: 2.7557x; 1.1132x over previous
#include <cuda_runtime.h>
#include <cuda_fp16.h>
#include <cstdint>

#define FULLMASK 0xffffffffu

// ---------------------------------------------------------------------------
// Device-global scratch (allocation-free rule). All fp16.
static __device__ __half g_Ah[4096 * 3072];   // concat [q|k|v]
static __device__ __half g_Wh[3072 * 3072];   // W_qkv
static __device__ __half g_Wph[1024 * 1024];  // W_proj
static __device__ __half g_Q[32 * 2048 * 64]; // [B*H, N, hd], scale folded in
static __device__ __half g_K[32 * 2048 * 64];
static __device__ __half g_V[32 * 2048 * 64];
static __device__ __half g_Xh[2 * 2048 * 1024];

__device__ __forceinline__ uint32_t smem_u32(const void* p) {
    uint32_t a;
    asm("{ .reg .u64 t; cvta.to.shared.u64 t, %1; cvt.u32.u64 %0, t; }"
        : "=r"(a) : "l"(p));
    return a;
}

#define CP_ASYNC16(dst, src) \
    asm volatile("cp.async.cg.shared.global [%0], [%1], 16;" :: "r"(dst), "l"(src))
#define CP_COMMIT() asm volatile("cp.async.commit_group;" ::: "memory")
#define CP_WAIT1()  asm volatile("cp.async.wait_group 1;"  ::: "memory")
#define CP_WAIT0()  asm volatile("cp.async.wait_group 0;"  ::: "memory")

#define LDSM_X4(r0, r1, r2, r3, addr) \
    asm volatile("ldmatrix.sync.aligned.m8n8.x4.shared.b16 {%0,%1,%2,%3}, [%4];" \
                 : "=r"(r0), "=r"(r1), "=r"(r2), "=r"(r3) : "r"(addr))

__device__ __forceinline__ void mma16(float c[4], const uint32_t a[4], const uint32_t b[2]) {
    asm volatile(
        "mma.sync.aligned.m16n8k16.row.col.f32.f16.f16.f32 "
        "{%0,%1,%2,%3}, {%4,%5,%6,%7}, {%8,%9}, {%0,%1,%2,%3};"
        : "+f"(c[0]), "+f"(c[1]), "+f"(c[2]), "+f"(c[3])
        : "r"(a[0]), "r"(a[1]), "r"(a[2]), "r"(a[3]), "r"(b[0]), "r"(b[1]));
}

__device__ __forceinline__ uint32_t pack_h2(float lo, float hi) {
    __half2 h = __floats2half2_rn(lo, hi);
    return *reinterpret_cast<uint32_t*>(&h);
}

// ---------------------------------------------------------------------------
// Prepass: fp32 -> fp16 conversions (done once; GEMMs re-read these 24-32x).
// ---------------------------------------------------------------------------
__global__ void cvt_A(const float* __restrict__ q, const float* __restrict__ k,
                      const float* __restrict__ v) {
    for (int i4 = (blockIdx.x * blockDim.x + threadIdx.x) * 4; i4 < 4096 * 3072;
         i4 += gridDim.x * blockDim.x * 4) {
        const int r = i4 / 3072;
        const int c = i4 - r * 3072;
        const float* s = ((c < 1024) ? q : ((c < 2048) ? k : v)) + (size_t)r * 1024 + (c & 1023);
        const float4 f = *(const float4*)s;
        __half2* d = (__half2*)&g_Ah[(size_t)r * 3072 + c];
        d[0] = __floats2half2_rn(f.x, f.y);
        d[1] = __floats2half2_rn(f.z, f.w);
    }
}

__global__ void cvt_Wqkv(const float* __restrict__ W) {
    for (int i4 = (blockIdx.x * blockDim.x + threadIdx.x) * 4; i4 < 3072 * 3072;
         i4 += gridDim.x * blockDim.x * 4) {
        const float4 f = *(const float4*)(W + i4);
        __half2* d = (__half2*)&g_Wh[i4];
        d[0] = __floats2half2_rn(f.x, f.y);
        d[1] = __floats2half2_rn(f.z, f.w);
    }
}

__global__ void cvt_Wp(const float* __restrict__ W) {
    for (int i4 = (blockIdx.x * blockDim.x + threadIdx.x) * 4; i4 < 1024 * 1024;
         i4 += gridDim.x * blockDim.x * 4) {
        const float4 f = *(const float4*)(W + i4);
        __half2* d = (__half2*)&g_Wph[i4];
        d[0] = __floats2half2_rn(f.x, f.y);
        d[1] = __floats2half2_rn(f.z, f.w);
    }
}

// ---------------------------------------------------------------------------
// fp16 NT GEMM with ldmatrix fragment loads.
// Block 128x128, BK=32, 256 threads (8 warps 4m x 2n), warp tile 32x64.
// 3-stage cp.async pipeline, padded rows (40 halfs = 80B) -> LDSM conflict-free.
// MODE 0: A=g_Ah, B=g_Wh, scatter fp16 to g_Q/g_K/g_V (Q scaled by 0.125).
// MODE 1: A=g_Xh, B=g_Wph, out = C + bias (fp32).
// ---------------------------------------------------------------------------
template <int MODE>
__global__ void __launch_bounds__(256, 2) gemm_h(const float* __restrict__ bias,
                                                 float* __restrict__ out)
{
    constexpr int KDIM = (MODE == 0) ? 3072 : 1024;
    constexpr int NK   = KDIM / 32;
    constexpr int STAGE_BYTES = 20480;   // A 10240 + B 10240

    extern __shared__ __align__(16) char sm[];
    const uint32_t sbase = smem_u32(sm);

    const __half* __restrict__ A = (MODE == 0) ? g_Ah : g_Xh;
    const __half* __restrict__ B = (MODE == 0) ? g_Wh : g_Wph;

    const int tid  = threadIdx.x;
    const int lane = tid & 31;
    const int w    = tid >> 5;
    const int gid  = lane >> 2;
    const int tig  = lane & 3;
    const int warp_m = (w >> 1) * 32;
    const int warp_n = (w & 1) * 64;
    const int mBase  = blockIdx.y * 128;
    const int nBase  = blockIdx.x * 128;

    // ldmatrix lane-address components
    const int row_in = lane & 7;
    const int sel    = lane >> 3;          // 0..3 tile selector
    // A x4 tiles: tile = (m + (sel&1)*8, k + (sel>>1)*8)
    const int a_row_off = (sel & 1) * 8 + row_in;      // within 16-row frag
    const int a_k_off   = (sel >> 1) * 8;              // halfs
    // B x4 tiles: tile = (n + (sel>>1)*8, k + (sel&1)*8)
    const int b_row_off = (sel >> 1) * 8 + row_in;
    const int b_k_off   = (sel & 1) * 8;

    auto stage = [&](int kt, int st) {
#pragma unroll
        for (int i = 0; i < 4; i++) {
            const int c   = tid + 256 * i;
            const int mat = c >> 9;          // 0=A, 1=B
            const int cc  = c & 511;
            const int row = cc >> 2;
            const int ch  = cc & 3;
            const __half* src = (mat == 0)
                ? (A + (size_t)(mBase + row) * KDIM + kt * 32 + ch * 8)
                : (B + (size_t)(nBase + row) * KDIM + kt * 32 + ch * 8);
            const uint32_t dst = sbase + st * STAGE_BYTES + mat * 10240 + row * 80 + ch * 16;
            CP_ASYNC16(dst, src);
        }
        CP_COMMIT();
    };

    float acc[2][8][4];
#pragma unroll
    for (int i = 0; i < 2; i++)
#pragma unroll
        for (int j = 0; j < 8; j++)
#pragma unroll
            for (int e = 0; e < 4; e++) acc[i][j][e] = 0.f;

    stage(0, 0);
    stage(1, 1);

    for (int kt = 0; kt < NK; kt++) {
        const int st = kt % 3;
        if (kt + 1 < NK) { CP_WAIT1(); } else { CP_WAIT0(); }
        __syncthreads();
        if (kt + 2 < NK) stage(kt + 2, (kt + 2) % 3);

        const uint32_t a_sm = sbase + st * STAGE_BYTES;
        const uint32_t b_sm = a_sm + 10240;

#pragma unroll
        for (int ks = 0; ks < 2; ks++) {
            uint32_t a[2][4], b[8][2];
#pragma unroll
            for (int mt = 0; mt < 2; mt++) {
                const uint32_t addr = a_sm +
                    (warp_m + mt * 16 + a_row_off) * 80 + (ks * 16 + a_k_off) * 2;
                LDSM_X4(a[mt][0], a[mt][1], a[mt][2], a[mt][3], addr);
            }
#pragma unroll
            for (int pr = 0; pr < 4; pr++) {   // n-tile pairs: covers nt=2pr, 2pr+1
                const uint32_t addr = b_sm +
                    (warp_n + pr * 16 + b_row_off) * 80 + (ks * 16 + b_k_off) * 2;
                LDSM_X4(b[2 * pr][0], b[2 * pr][1], b[2 * pr + 1][0], b[2 * pr + 1][1], addr);
            }
#pragma unroll
            for (int mt = 0; mt < 2; mt++)
#pragma unroll
                for (int nt = 0; nt < 8; nt++)
                    mma16(acc[mt][nt], a[mt], b[nt]);
        }
    }

    // Epilogue. C frag: c0(row g, col 2t), c1(g, 2t+1), c2(g+8, 2t), c3(g+8, 2t+1).
#pragma unroll
    for (int mt = 0; mt < 2; mt++) {
        const int row0 = mBase + warp_m + mt * 16 + gid;
#pragma unroll
        for (int nt = 0; nt < 8; nt++) {
            const int col = nBase + warp_n + nt * 8 + 2 * tig;
            if (MODE == 0) {
                const int t = col >> 10, hh = (col >> 6) & 15, d = col & 63;
                const float sc = (t == 0) ? 0.125f : 1.f;
                __half* dst = ((t == 0) ? g_Q : ((t == 1) ? g_K : g_V)) +
                    ((size_t)((row0 >> 11) * 16 + hh) * 2048 + (row0 & 2047)) * 64 + d;
                *(__half2*)dst =
                    __floats2half2_rn(acc[mt][nt][0] * sc, acc[mt][nt][1] * sc);
                *(__half2*)(dst + 8 * 64) =
                    __floats2half2_rn(acc[mt][nt][2] * sc, acc[mt][nt][3] * sc);
            } else {
                const float b0 = bias[col], b1 = bias[col + 1];
                *(float2*)(out + (size_t)row0 * 1024 + col) =
                    make_float2(acc[mt][nt][0] + b0, acc[mt][nt][1] + b1);
                *(float2*)(out + (size_t)(row0 + 8) * 1024 + col) =
                    make_float2(acc[mt][nt][2] + b0, acc[mt][nt][3] + b1);
            }
        }
    }
}

// ---------------------------------------------------------------------------
// fp16 flash attention: grid (16, 32), 256 threads. K frags via ldmatrix.x4.
// ---------------------------------------------------------------------------
__global__ void __launch_bounds__(256) attn_flash_h()
{
    constexpr int KV_BYTES = 9216;       // 64 rows x 72 halfs (144B)
    constexpr int STAGE_BYTES = 2 * KV_BYTES;
    extern __shared__ __align__(16) char sm[];
    const uint32_t sbase = smem_u32(sm);

    const int bh    = blockIdx.y;
    const int qbase = blockIdx.x * 128;
    const int tid   = threadIdx.x;
    const int lane  = tid & 31;
    const int w     = tid >> 5;
    const int gid   = lane >> 2;
    const int tig   = lane & 3;

    const int row_in = lane & 7;
    const int sel    = lane >> 3;
    const int b_row_off = (sel >> 1) * 8 + row_in;
    const int b_k_off   = (sel & 1) * 8;

    const __half* Kp = g_K + (size_t)bh * (2048 * 64);
    const __half* Vp = g_V + (size_t)bh * (2048 * 64);

    auto stage = [&](int kv_tile, int st) {
#pragma unroll
        for (int i = 0; i < 4; i++) {
            const int c   = tid + 256 * i;
            const int mat = c >> 9;          // 0=K, 1=V
            const int cc  = c & 511;
            const int row = cc >> 3;
            const int ch  = cc & 7;
            const __half* src = ((mat == 0) ? Kp : Vp) +
                (size_t)(kv_tile * 64 + row) * 64 + ch * 8;
            const uint32_t dst = sbase + st * STAGE_BYTES + mat * KV_BYTES + row * 144 + ch * 16;
            CP_ASYNC16(dst, src);
        }
        CP_COMMIT();
    };

    uint32_t qa[4][4];
    {
        const __half* q0 = g_Q + ((size_t)bh * 2048 + qbase + w * 16 + gid) * 64;
#pragma unroll
        for (int s = 0; s < 4; s++) {
            qa[s][0] = *(const uint32_t*)(q0 + s * 16 + 2 * tig);
            qa[s][1] = *(const uint32_t*)(q0 + 8 * 64 + s * 16 + 2 * tig);
            qa[s][2] = *(const uint32_t*)(q0 + s * 16 + 2 * tig + 8);
            qa[s][3] = *(const uint32_t*)(q0 + 8 * 64 + s * 16 + 2 * tig + 8);
        }
    }

    float o[8][4];
#pragma unroll
    for (int i = 0; i < 8; i++)
#pragma unroll
        for (int j = 0; j < 4; j++) o[i][j] = 0.f;
    float m0 = -1e30f, m1 = -1e30f, l0 = 0.f, l1 = 0.f;

    stage(0, 0);
    stage(1, 1);

    for (int it = 0; it < 32; it++) {
        const int st = it % 3;
        if (it + 1 < 32) { CP_WAIT1(); } else { CP_WAIT0(); }
        __syncthreads();
        if (it + 2 < 32) stage(it + 2, (it + 2) % 3);

        const uint32_t ksb = sbase + st * STAGE_BYTES;
        const uint32_t vsb = ksb + KV_BYTES;

        float s[8][4];
#pragma unroll
        for (int i = 0; i < 8; i++)
#pragma unroll
            for (int j = 0; j < 4; j++) s[i][j] = 0.f;
#pragma unroll
        for (int ks = 0; ks < 4; ks++) {
            uint32_t b[8][2];
#pragma unroll
            for (int pr = 0; pr < 4; pr++) {
                const uint32_t addr = ksb +
                    (pr * 16 + b_row_off) * 144 + (ks * 16 + b_k_off) * 2;
                LDSM_X4(b[2 * pr][0], b[2 * pr][1], b[2 * pr + 1][0], b[2 * pr + 1][1], addr);
            }
#pragma unroll
            for (int nt = 0; nt < 8; nt++)
                mma16(s[nt], qa[ks], b[nt]);
        }

        float mt0 = -1e30f, mt1 = -1e30f;
#pragma unroll
        for (int nt = 0; nt < 8; nt++) {
            mt0 = fmaxf(mt0, fmaxf(s[nt][0], s[nt][1]));
            mt1 = fmaxf(mt1, fmaxf(s[nt][2], s[nt][3]));
        }
        mt0 = fmaxf(mt0, __shfl_xor_sync(FULLMASK, mt0, 1));
        mt0 = fmaxf(mt0, __shfl_xor_sync(FULLMASK, mt0, 2));
        mt1 = fmaxf(mt1, __shfl_xor_sync(FULLMASK, mt1, 1));
        mt1 = fmaxf(mt1, __shfl_xor_sync(FULLMASK, mt1, 2));

        const float mn0 = fmaxf(m0, mt0), mn1 = fmaxf(m1, mt1);
        const float f0 = __expf(m0 - mn0), f1 = __expf(m1 - mn1);

        float rs0 = 0.f, rs1 = 0.f;
#pragma unroll
        for (int nt = 0; nt < 8; nt++) {
            s[nt][0] = __expf(s[nt][0] - mn0);
            s[nt][1] = __expf(s[nt][1] - mn0);
            s[nt][2] = __expf(s[nt][2] - mn1);
            s[nt][3] = __expf(s[nt][3] - mn1);
            rs0 += s[nt][0] + s[nt][1];
            rs1 += s[nt][2] + s[nt][3];
        }
        rs0 += __shfl_xor_sync(FULLMASK, rs0, 1);
        rs0 += __shfl_xor_sync(FULLMASK, rs0, 2);
        rs1 += __shfl_xor_sync(FULLMASK, rs1, 1);
        rs1 += __shfl_xor_sync(FULLMASK, rs1, 2);

        l0 = l0 * f0 + rs0;
        l1 = l1 * f1 + rs1;
        m0 = mn0;
        m1 = mn1;
#pragma unroll
        for (int nt = 0; nt < 8; nt++) {
            o[nt][0] *= f0; o[nt][1] *= f0;
            o[nt][2] *= f1; o[nt][3] *= f1;
        }

#pragma unroll
        for (int kt = 0; kt < 4; kt++) {
            uint32_t pa[4];
            pa[0] = pack_h2(s[2 * kt][0],     s[2 * kt][1]);
            pa[1] = pack_h2(s[2 * kt][2],     s[2 * kt][3]);
            pa[2] = pack_h2(s[2 * kt + 1][0], s[2 * kt + 1][1]);
            pa[3] = pack_h2(s[2 * kt + 1][2], s[2 * kt + 1][3]);
#pragma unroll
            for (int nt = 0; nt < 8; nt++) {
                const uint32_t addr = vsb + (kt * 16 + (lane & 15)) * 144 + nt * 16;
                uint32_t b0, b1;
                asm volatile(
                    "ldmatrix.sync.aligned.m8n8.x2.trans.shared.b16 {%0,%1}, [%2];"
                    : "=r"(b0), "=r"(b1) : "r"(addr));
                uint32_t b[2] = {b0, b1};
                mma16(o[nt], pa, b);
            }
        }
    }

    const float inv0 = 1.f / l0, inv1 = 1.f / l1;
    const int b = bh >> 4, h = bh & 15;
    const int n0 = qbase + w * 16 + gid;
    __half* x0 = g_Xh + ((size_t)b * 2048 + n0) * 1024 + h * 64;
    __half* x8 = x0 + 8 * 1024;
#pragma unroll
    for (int nt = 0; nt < 8; nt++) {
        const int d = nt * 8 + 2 * tig;
        *(__half2*)(x0 + d) = __floats2half2_rn(o[nt][0] * inv0, o[nt][1] * inv0);
        *(__half2*)(x8 + d) = __floats2half2_rn(o[nt][2] * inv1, o[nt][3] * inv1);
    }
}

// ---------------------------------------------------------------------------
extern "C" void kernel_launch(void* const* d_in, const int* in_sizes, int n_in,
                              void* d_out, int out_size)
{
    const float* q     = (const float*)d_in[0];
    const float* k     = (const float*)d_in[1];
    const float* v     = (const float*)d_in[2];
    const float* Wqkv  = (const float*)d_in[3];
    const float* Wproj = (const float*)d_in[4];
    const float* bproj = (const float*)d_in[5];
    float* out = (float*)d_out;

    static bool attr_done = false;
    const int GEMM_SMEM = 3 * 20480;   // 61440
    const int ATTN_SMEM = 3 * 18432;   // 55296
    if (!attr_done) {
        cudaFuncSetAttribute(gemm_h<0>, cudaFuncAttributeMaxDynamicSharedMemorySize, GEMM_SMEM);
        cudaFuncSetAttribute(gemm_h<1>, cudaFuncAttributeMaxDynamicSharedMemorySize, GEMM_SMEM);
        cudaFuncSetAttribute(attn_flash_h, cudaFuncAttributeMaxDynamicSharedMemorySize, ATTN_SMEM);
        attr_done = true;
    }

    // 0) fp32 -> fp16 prepass
    cvt_A<<<2048, 256>>>(q, k, v);
    cvt_Wqkv<<<2048, 256>>>(Wqkv);
    cvt_Wp<<<512, 256>>>(Wproj);
    // 1) fused QKV projection -> g_Q/g_K/g_V (fp16, Q pre-scaled)
    gemm_h<0><<<dim3(24, 32), 256, GEMM_SMEM>>>(nullptr, nullptr);
    // 2) flash attention -> g_Xh (fp16)
    attn_flash_h<<<dim3(16, 32), 256, ATTN_SMEM>>>();
    // 3) output projection + bias -> d_out (fp32)
    gemm_h<1><<<dim3(8, 32), 256, GEMM_SMEM>>>(bproj, out);
}

// round 7
// speedup vs baseline: 2.9236x; 1.0609x over previous
#include <cuda_runtime.h>
#include <cuda_fp16.h>
#include <cstdint>

#define FULLMASK 0xffffffffu

// ---------------------------------------------------------------------------
// Device-global scratch (allocation-free rule). All fp16.
static __device__ __half g_Ah[4096 * 3072];   // concat [q|k|v]
static __device__ __half g_Wh[3072 * 3072];   // W_qkv
static __device__ __half g_Wph[1024 * 1024];  // W_proj
static __device__ __half g_Q[32 * 2048 * 64]; // [B*H, N, hd], scale folded in
static __device__ __half g_K[32 * 2048 * 64];
static __device__ __half g_V[32 * 2048 * 64];
static __device__ __half g_Xh[2 * 2048 * 1024];

__device__ __forceinline__ uint32_t smem_u32(const void* p) {
    uint32_t a;
    asm("{ .reg .u64 t; cvta.to.shared.u64 t, %1; cvt.u32.u64 %0, t; }"
        : "=r"(a) : "l"(p));
    return a;
}

#define CP_ASYNC16(dst, src) \
    asm volatile("cp.async.cg.shared.global [%0], [%1], 16;" :: "r"(dst), "l"(src))
#define CP_COMMIT() asm volatile("cp.async.commit_group;" ::: "memory")
#define CP_WAIT1()  asm volatile("cp.async.wait_group 1;"  ::: "memory")
#define CP_WAIT0()  asm volatile("cp.async.wait_group 0;"  ::: "memory")

#define LDSM_X4(r0, r1, r2, r3, addr) \
    asm volatile("ldmatrix.sync.aligned.m8n8.x4.shared.b16 {%0,%1,%2,%3}, [%4];" \
                 : "=r"(r0), "=r"(r1), "=r"(r2), "=r"(r3) : "r"(addr))

__device__ __forceinline__ void mma16(float c[4], const uint32_t a[4], const uint32_t b[2]) {
    asm volatile(
        "mma.sync.aligned.m16n8k16.row.col.f32.f16.f16.f32 "
        "{%0,%1,%2,%3}, {%4,%5,%6,%7}, {%8,%9}, {%0,%1,%2,%3};"
        : "+f"(c[0]), "+f"(c[1]), "+f"(c[2]), "+f"(c[3])
        : "r"(a[0]), "r"(a[1]), "r"(a[2]), "r"(a[3]), "r"(b[0]), "r"(b[1]));
}

__device__ __forceinline__ uint32_t pack_h2(float lo, float hi) {
    __half2 h = __floats2half2_rn(lo, hi);
    return *reinterpret_cast<uint32_t*>(&h);
}

// ---------------------------------------------------------------------------
// Prepass: fp32 -> fp16 conversions (done once; GEMMs re-read these 24-32x).
// ---------------------------------------------------------------------------
__global__ void cvt_A(const float* __restrict__ q, const float* __restrict__ k,
                      const float* __restrict__ v) {
    for (int i4 = (blockIdx.x * blockDim.x + threadIdx.x) * 4; i4 < 4096 * 3072;
         i4 += gridDim.x * blockDim.x * 4) {
        const int r = i4 / 3072;
        const int c = i4 - r * 3072;
        const float* s = ((c < 1024) ? q : ((c < 2048) ? k : v)) + (size_t)r * 1024 + (c & 1023);
        const float4 f = *(const float4*)s;
        __half2* d = (__half2*)&g_Ah[(size_t)r * 3072 + c];
        d[0] = __floats2half2_rn(f.x, f.y);
        d[1] = __floats2half2_rn(f.z, f.w);
    }
}

__global__ void cvt_Wqkv(const float* __restrict__ W) {
    for (int i4 = (blockIdx.x * blockDim.x + threadIdx.x) * 4; i4 < 3072 * 3072;
         i4 += gridDim.x * blockDim.x * 4) {
        const float4 f = *(const float4*)(W + i4);
        __half2* d = (__half2*)&g_Wh[i4];
        d[0] = __floats2half2_rn(f.x, f.y);
        d[1] = __floats2half2_rn(f.z, f.w);
    }
}

__global__ void cvt_Wp(const float* __restrict__ W) {
    for (int i4 = (blockIdx.x * blockDim.x + threadIdx.x) * 4; i4 < 1024 * 1024;
         i4 += gridDim.x * blockDim.x * 4) {
        const float4 f = *(const float4*)(W + i4);
        __half2* d = (__half2*)&g_Wph[i4];
        d[0] = __floats2half2_rn(f.x, f.y);
        d[1] = __floats2half2_rn(f.z, f.w);
    }
}

// ---------------------------------------------------------------------------
// fp16 NT GEMM, ldmatrix fragments, BK=64, 2-stage double buffer.
// Block 128x128, 256 threads (8 warps 4m x 2n), warp tile 32x64.
// Per K-tile: 1 barrier for 4 ks-steps (64 MMA) -- barrier amortization.
// Rows padded to 72 halfs (144B): LDSM + cp.async conflict-free.
// MODE 0: A=g_Ah, B=g_Wh, scatter fp16 to g_Q/g_K/g_V (Q scaled by 0.125).
// MODE 1: A=g_Xh, B=g_Wph, out = C + bias (fp32).
// ---------------------------------------------------------------------------
template <int MODE>
__global__ void __launch_bounds__(256, 2) gemm_h(const float* __restrict__ bias,
                                                 float* __restrict__ out)
{
    constexpr int KDIM = (MODE == 0) ? 3072 : 1024;
    constexpr int NK   = KDIM / 64;
    constexpr int TILE_BYTES  = 128 * 144;        // 18432 per matrix
    constexpr int STAGE_BYTES = 2 * TILE_BYTES;   // 36864

    extern __shared__ __align__(16) char sm[];
    const uint32_t sbase = smem_u32(sm);

    const __half* __restrict__ A = (MODE == 0) ? g_Ah : g_Xh;
    const __half* __restrict__ B = (MODE == 0) ? g_Wh : g_Wph;

    const int tid  = threadIdx.x;
    const int lane = tid & 31;
    const int w    = tid >> 5;
    const int gid  = lane >> 2;
    const int tig  = lane & 3;
    const int warp_m = (w >> 1) * 32;
    const int warp_n = (w & 1) * 64;
    const int mBase  = blockIdx.y * 128;
    const int nBase  = blockIdx.x * 128;

    // ldmatrix lane-address components
    const int row_in = lane & 7;
    const int sel    = lane >> 3;
    const int a_row_off = (sel & 1) * 8 + row_in;
    const int a_k_off   = (sel >> 1) * 8;
    const int b_row_off = (sel >> 1) * 8 + row_in;
    const int b_k_off   = (sel & 1) * 8;

    auto stage = [&](int kt, int st) {
#pragma unroll
        for (int i = 0; i < 8; i++) {
            const int c   = tid + 256 * i;       // 0..2047
            const int mat = c >> 10;             // 0=A, 1=B
            const int cc  = c & 1023;
            const int row = cc >> 3;
            const int ch  = cc & 7;
            const __half* src = (mat == 0)
                ? (A + (size_t)(mBase + row) * KDIM + kt * 64 + ch * 8)
                : (B + (size_t)(nBase + row) * KDIM + kt * 64 + ch * 8);
            const uint32_t dst = sbase + st * STAGE_BYTES + mat * TILE_BYTES
                               + row * 144 + ch * 16;
            CP_ASYNC16(dst, src);
        }
        CP_COMMIT();
    };

    float acc[2][8][4];
#pragma unroll
    for (int i = 0; i < 2; i++)
#pragma unroll
        for (int j = 0; j < 8; j++)
#pragma unroll
            for (int e = 0; e < 4; e++) acc[i][j][e] = 0.f;

    stage(0, 0);

    for (int kt = 0; kt < NK; kt++) {
        const int st = kt & 1;
        CP_WAIT0();          // loads for tile kt (issued last iteration) complete
        __syncthreads();     // all warps done reading buffer st^1 -> safe to refill
        if (kt + 1 < NK) stage(kt + 1, st ^ 1);

        const uint32_t a_sm = sbase + st * STAGE_BYTES;
        const uint32_t b_sm = a_sm + TILE_BYTES;

#pragma unroll
        for (int ks = 0; ks < 4; ks++) {
            uint32_t a[2][4], b[8][2];
#pragma unroll
            for (int mt = 0; mt < 2; mt++) {
                const uint32_t addr = a_sm +
                    (warp_m + mt * 16 + a_row_off) * 144 + (ks * 16 + a_k_off) * 2;
                LDSM_X4(a[mt][0], a[mt][1], a[mt][2], a[mt][3], addr);
            }
#pragma unroll
            for (int pr = 0; pr < 4; pr++) {
                const uint32_t addr = b_sm +
                    (warp_n + pr * 16 + b_row_off) * 144 + (ks * 16 + b_k_off) * 2;
                LDSM_X4(b[2 * pr][0], b[2 * pr][1], b[2 * pr + 1][0], b[2 * pr + 1][1], addr);
            }
#pragma unroll
            for (int mt = 0; mt < 2; mt++)
#pragma unroll
                for (int nt = 0; nt < 8; nt++)
                    mma16(acc[mt][nt], a[mt], b[nt]);
        }
    }

    // Epilogue. C frag: c0(row g, col 2t), c1(g, 2t+1), c2(g+8, 2t), c3(g+8, 2t+1).
#pragma unroll
    for (int mt = 0; mt < 2; mt++) {
        const int row0 = mBase + warp_m + mt * 16 + gid;
#pragma unroll
        for (int nt = 0; nt < 8; nt++) {
            const int col = nBase + warp_n + nt * 8 + 2 * tig;
            if (MODE == 0) {
                const int t = col >> 10, hh = (col >> 6) & 15, d = col & 63;
                const float sc = (t == 0) ? 0.125f : 1.f;
                __half* dst = ((t == 0) ? g_Q : ((t == 1) ? g_K : g_V)) +
                    ((size_t)((row0 >> 11) * 16 + hh) * 2048 + (row0 & 2047)) * 64 + d;
                *(__half2*)dst =
                    __floats2half2_rn(acc[mt][nt][0] * sc, acc[mt][nt][1] * sc);
                *(__half2*)(dst + 8 * 64) =
                    __floats2half2_rn(acc[mt][nt][2] * sc, acc[mt][nt][3] * sc);
            } else {
                const float b0 = bias[col], b1 = bias[col + 1];
                *(float2*)(out + (size_t)row0 * 1024 + col) =
                    make_float2(acc[mt][nt][0] + b0, acc[mt][nt][1] + b1);
                *(float2*)(out + (size_t)(row0 + 8) * 1024 + col) =
                    make_float2(acc[mt][nt][2] + b0, acc[mt][nt][3] + b1);
            }
        }
    }
}

// ---------------------------------------------------------------------------
// fp16 flash attention (unchanged from R6): grid (16, 32), 256 threads.
// ---------------------------------------------------------------------------
__global__ void __launch_bounds__(256) attn_flash_h()
{
    constexpr int KV_BYTES = 9216;       // 64 rows x 72 halfs (144B)
    constexpr int STAGE_BYTES = 2 * KV_BYTES;
    extern __shared__ __align__(16) char sm[];
    const uint32_t sbase = smem_u32(sm);

    const int bh    = blockIdx.y;
    const int qbase = blockIdx.x * 128;
    const int tid   = threadIdx.x;
    const int lane  = tid & 31;
    const int w     = tid >> 5;
    const int gid   = lane >> 2;
    const int tig   = lane & 3;

    const int row_in = lane & 7;
    const int sel    = lane >> 3;
    const int b_row_off = (sel >> 1) * 8 + row_in;
    const int b_k_off   = (sel & 1) * 8;

    const __half* Kp = g_K + (size_t)bh * (2048 * 64);
    const __half* Vp = g_V + (size_t)bh * (2048 * 64);

    auto stage = [&](int kv_tile, int st) {
#pragma unroll
        for (int i = 0; i < 4; i++) {
            const int c   = tid + 256 * i;
            const int mat = c >> 9;          // 0=K, 1=V
            const int cc  = c & 511;
            const int row = cc >> 3;
            const int ch  = cc & 7;
            const __half* src = ((mat == 0) ? Kp : Vp) +
                (size_t)(kv_tile * 64 + row) * 64 + ch * 8;
            const uint32_t dst = sbase + st * STAGE_BYTES + mat * KV_BYTES + row * 144 + ch * 16;
            CP_ASYNC16(dst, src);
        }
        CP_COMMIT();
    };

    uint32_t qa[4][4];
    {
        const __half* q0 = g_Q + ((size_t)bh * 2048 + qbase + w * 16 + gid) * 64;
#pragma unroll
        for (int s = 0; s < 4; s++) {
            qa[s][0] = *(const uint32_t*)(q0 + s * 16 + 2 * tig);
            qa[s][1] = *(const uint32_t*)(q0 + 8 * 64 + s * 16 + 2 * tig);
            qa[s][2] = *(const uint32_t*)(q0 + s * 16 + 2 * tig + 8);
            qa[s][3] = *(const uint32_t*)(q0 + 8 * 64 + s * 16 + 2 * tig + 8);
        }
    }

    float o[8][4];
#pragma unroll
    for (int i = 0; i < 8; i++)
#pragma unroll
        for (int j = 0; j < 4; j++) o[i][j] = 0.f;
    float m0 = -1e30f, m1 = -1e30f, l0 = 0.f, l1 = 0.f;

    stage(0, 0);
    stage(1, 1);

    for (int it = 0; it < 32; it++) {
        const int st = it % 3;
        if (it + 1 < 32) { CP_WAIT1(); } else { CP_WAIT0(); }
        __syncthreads();
        if (it + 2 < 32) stage(it + 2, (it + 2) % 3);

        const uint32_t ksb = sbase + st * STAGE_BYTES;
        const uint32_t vsb = ksb + KV_BYTES;

        float s[8][4];
#pragma unroll
        for (int i = 0; i < 8; i++)
#pragma unroll
            for (int j = 0; j < 4; j++) s[i][j] = 0.f;
#pragma unroll
        for (int ks = 0; ks < 4; ks++) {
            uint32_t b[8][2];
#pragma unroll
            for (int pr = 0; pr < 4; pr++) {
                const uint32_t addr = ksb +
                    (pr * 16 + b_row_off) * 144 + (ks * 16 + b_k_off) * 2;
                LDSM_X4(b[2 * pr][0], b[2 * pr][1], b[2 * pr + 1][0], b[2 * pr + 1][1], addr);
            }
#pragma unroll
            for (int nt = 0; nt < 8; nt++)
                mma16(s[nt], qa[ks], b[nt]);
        }

        float mt0 = -1e30f, mt1 = -1e30f;
#pragma unroll
        for (int nt = 0; nt < 8; nt++) {
            mt0 = fmaxf(mt0, fmaxf(s[nt][0], s[nt][1]));
            mt1 = fmaxf(mt1, fmaxf(s[nt][2], s[nt][3]));
        }
        mt0 = fmaxf(mt0, __shfl_xor_sync(FULLMASK, mt0, 1));
        mt0 = fmaxf(mt0, __shfl_xor_sync(FULLMASK, mt0, 2));
        mt1 = fmaxf(mt1, __shfl_xor_sync(FULLMASK, mt1, 1));
        mt1 = fmaxf(mt1, __shfl_xor_sync(FULLMASK, mt1, 2));

        const float mn0 = fmaxf(m0, mt0), mn1 = fmaxf(m1, mt1);
        const float f0 = __expf(m0 - mn0), f1 = __expf(m1 - mn1);

        float rs0 = 0.f, rs1 = 0.f;
#pragma unroll
        for (int nt = 0; nt < 8; nt++) {
            s[nt][0] = __expf(s[nt][0] - mn0);
            s[nt][1] = __expf(s[nt][1] - mn0);
            s[nt][2] = __expf(s[nt][2] - mn1);
            s[nt][3] = __expf(s[nt][3] - mn1);
            rs0 += s[nt][0] + s[nt][1];
            rs1 += s[nt][2] + s[nt][3];
        }
        rs0 += __shfl_xor_sync(FULLMASK, rs0, 1);
        rs0 += __shfl_xor_sync(FULLMASK, rs0, 2);
        rs1 += __shfl_xor_sync(FULLMASK, rs1, 1);
        rs1 += __shfl_xor_sync(FULLMASK, rs1, 2);

        l0 = l0 * f0 + rs0;
        l1 = l1 * f1 + rs1;
        m0 = mn0;
        m1 = mn1;
#pragma unroll
        for (int nt = 0; nt < 8; nt++) {
            o[nt][0] *= f0; o[nt][1] *= f0;
            o[nt][2] *= f1; o[nt][3] *= f1;
        }

#pragma unroll
        for (int kt = 0; kt < 4; kt++) {
            uint32_t pa[4];
            pa[0] = pack_h2(s[2 * kt][0],     s[2 * kt][1]);
            pa[1] = pack_h2(s[2 * kt][2],     s[2 * kt][3]);
            pa[2] = pack_h2(s[2 * kt + 1][0], s[2 * kt + 1][1]);
            pa[3] = pack_h2(s[2 * kt + 1][2], s[2 * kt + 1][3]);
#pragma unroll
            for (int nt = 0; nt < 8; nt++) {
                const uint32_t addr = vsb + (kt * 16 + (lane & 15)) * 144 + nt * 16;
                uint32_t b0, b1;
                asm volatile(
                    "ldmatrix.sync.aligned.m8n8.x2.trans.shared.b16 {%0,%1}, [%2];"
                    : "=r"(b0), "=r"(b1) : "r"(addr));
                uint32_t b[2] = {b0, b1};
                mma16(o[nt], pa, b);
            }
        }
    }

    const float inv0 = 1.f / l0, inv1 = 1.f / l1;
    const int b = bh >> 4, h = bh & 15;
    const int n0 = qbase + w * 16 + gid;
    __half* x0 = g_Xh + ((size_t)b * 2048 + n0) * 1024 + h * 64;
    __half* x8 = x0 + 8 * 1024;
#pragma unroll
    for (int nt = 0; nt < 8; nt++) {
        const int d = nt * 8 + 2 * tig;
        *(__half2*)(x0 + d) = __floats2half2_rn(o[nt][0] * inv0, o[nt][1] * inv0);
        *(__half2*)(x8 + d) = __floats2half2_rn(o[nt][2] * inv1, o[nt][3] * inv1);
    }
}

// ---------------------------------------------------------------------------
extern "C" void kernel_launch(void* const* d_in, const int* in_sizes, int n_in,
                              void* d_out, int out_size)
{
    const float* q     = (const float*)d_in[0];
    const float* k     = (const float*)d_in[1];
    const float* v     = (const float*)d_in[2];
    const float* Wqkv  = (const float*)d_in[3];
    const float* Wproj = (const float*)d_in[4];
    const float* bproj = (const float*)d_in[5];
    float* out = (float*)d_out;

    static bool attr_done = false;
    const int GEMM_SMEM = 2 * 36864;   // 73728 (2-stage, BK=64)
    const int ATTN_SMEM = 3 * 18432;   // 55296
    if (!attr_done) {
        cudaFuncSetAttribute(gemm_h<0>, cudaFuncAttributeMaxDynamicSharedMemorySize, GEMM_SMEM);
        cudaFuncSetAttribute(gemm_h<1>, cudaFuncAttributeMaxDynamicSharedMemorySize, GEMM_SMEM);
        cudaFuncSetAttribute(attn_flash_h, cudaFuncAttributeMaxDynamicSharedMemorySize, ATTN_SMEM);
        attr_done = true;
    }

    // 0) fp32 -> fp16 prepass
    cvt_A<<<2048, 256>>>(q, k, v);
    cvt_Wqkv<<<2048, 256>>>(Wqkv);
    cvt_Wp<<<512, 256>>>(Wproj);
    // 1) fused QKV projection -> g_Q/g_K/g_V (fp16, Q pre-scaled)
    gemm_h<0><<<dim3(24, 32), 256, GEMM_SMEM>>>(nullptr, nullptr);
    // 2) flash attention -> g_Xh (fp16)
    attn_flash_h<<<dim3(16, 32), 256, ATTN_SMEM>>>();
    // 3) output projection + bias -> d_out (fp32)
    gemm_h<1><<<dim3(8, 32), 256, GEMM_SMEM>>>(bproj, out);
}